// round 2
// baseline (speedup 1.0000x reference)
#include <cuda_runtime.h>
#include <cuda_bf16.h>
#include <cstdint>

#define B_   2
#define N_   1024
#define DM   640
#define SH   5
#define DH   128
#define NH   14
#define KC   32

// -------- device scratch (no allocation allowed) --------
__device__ float g_qproj[B_ * N_ * SH * DH];   // (b,n,s,o)
__device__ float g_kproj[B_ * N_ * SH * DH];   // (b,n,s,o)
__device__ float g_vproj[B_ * N_ * NH * DH];   // (b,n,h,o)
__device__ float g_attn [B_ * N_ * NH * DH];   // (b,n,h,d)
__device__ float g_w    [B_ * N_ * NH * KC];   // softmax weights

__constant__ int c_dil [SH] = {1, 1, 2, 4, 8};
__constant__ int c_sub [NH] = {0,0,0,0,0, 1,1,1,1,1, 2,2, 3, 4};
__constant__ int c_dilh[NH] = {1,1,1,1,1, 1,1,1,1,1, 2,2, 4, 8};

// ---------------------------------------------------------------------------
// Double-buffered SGEMM, 128x128 tile, BK=8, 256 threads, 8x8 microtile.
// C[m,o] = sum_d A[m,d]*W[o,d] + bias[o].  M%128==0, Nout%128==0, K%8==0.
// ---------------------------------------------------------------------------
__global__ __launch_bounds__(256) void gemm128_kernel(
    const float* __restrict__ A, const float* __restrict__ W,
    const float* __restrict__ bias, float* __restrict__ C,
    int M, int Nout, int K)
{
    __shared__ float As[2][8][128];
    __shared__ float Ws[2][8][128];

    const int bm  = blockIdx.y * 128;
    const int bn  = blockIdx.x * 128;
    const int tid = threadIdx.x;
    const int tx  = tid & 15;
    const int ty  = tid >> 4;

    const int lr = tid >> 1;
    const int lc = (tid & 1) * 4;

    const float* Ap = A + (size_t)(bm + lr) * K + lc;
    const float* Wp = W + (size_t)(bn + lr) * K + lc;

    float acc[8][8];
#pragma unroll
    for (int i = 0; i < 8; i++)
#pragma unroll
        for (int j = 0; j < 8; j++) acc[i][j] = 0.0f;

    // prologue
    float4 a = *reinterpret_cast<const float4*>(Ap);
    float4 w = *reinterpret_cast<const float4*>(Wp);
    As[0][lc+0][lr] = a.x; As[0][lc+1][lr] = a.y;
    As[0][lc+2][lr] = a.z; As[0][lc+3][lr] = a.w;
    Ws[0][lc+0][lr] = w.x; Ws[0][lc+1][lr] = w.y;
    Ws[0][lc+2][lr] = w.z; Ws[0][lc+3][lr] = w.w;
    __syncthreads();

    const int nk = K >> 3;
    for (int it = 0; it < nk; it++) {
        const int cur = it & 1, nxt = cur ^ 1;
        if (it + 1 < nk) {
            a = *reinterpret_cast<const float4*>(Ap + (it + 1) * 8);
            w = *reinterpret_cast<const float4*>(Wp + (it + 1) * 8);
        }
#pragma unroll
        for (int kk = 0; kk < 8; kk++) {
            float af[8], wf[8];
            *reinterpret_cast<float4*>(af)     = *reinterpret_cast<const float4*>(&As[cur][kk][ty*8]);
            *reinterpret_cast<float4*>(af + 4) = *reinterpret_cast<const float4*>(&As[cur][kk][ty*8+4]);
            *reinterpret_cast<float4*>(wf)     = *reinterpret_cast<const float4*>(&Ws[cur][kk][tx*8]);
            *reinterpret_cast<float4*>(wf + 4) = *reinterpret_cast<const float4*>(&Ws[cur][kk][tx*8+4]);
#pragma unroll
            for (int i = 0; i < 8; i++)
#pragma unroll
                for (int j = 0; j < 8; j++) acc[i][j] += af[i] * wf[j];
        }
        if (it + 1 < nk) {
            As[nxt][lc+0][lr] = a.x; As[nxt][lc+1][lr] = a.y;
            As[nxt][lc+2][lr] = a.z; As[nxt][lc+3][lr] = a.w;
            Ws[nxt][lc+0][lr] = w.x; Ws[nxt][lc+1][lr] = w.y;
            Ws[nxt][lc+2][lr] = w.z; Ws[nxt][lc+3][lr] = w.w;
        }
        __syncthreads();
    }

#pragma unroll
    for (int i = 0; i < 8; i++) {
        const int row = bm + ty * 8 + i;
        const float* bp = bias + bn + tx * 8;
        float* cp = C + (size_t)row * Nout + bn + tx * 8;
        float4 b0 = *reinterpret_cast<const float4*>(bp);
        float4 b1 = *reinterpret_cast<const float4*>(bp + 4);
        float4 o0 = {acc[i][0]+b0.x, acc[i][1]+b0.y, acc[i][2]+b0.z, acc[i][3]+b0.w};
        float4 o1 = {acc[i][4]+b1.x, acc[i][5]+b1.y, acc[i][6]+b1.z, acc[i][7]+b1.w};
        *reinterpret_cast<float4*>(cp)     = o0;
        *reinterpret_cast<float4*>(cp + 4) = o1;
    }
}

// ---------------------------------------------------------------------------
// Double-buffered SGEMM, 64x128 tile, BK=8, 256 threads, 4x8 microtile.
// Used for N=640 GEMMs so the grid reaches 160 CTAs.
// ---------------------------------------------------------------------------
__global__ __launch_bounds__(256) void gemm64_kernel(
    const float* __restrict__ A, const float* __restrict__ W,
    const float* __restrict__ bias, float* __restrict__ C,
    int M, int Nout, int K)
{
    __shared__ float As[2][8][64];
    __shared__ float Ws[2][8][128];

    const int bm  = blockIdx.y * 64;
    const int bn  = blockIdx.x * 128;
    const int tid = threadIdx.x;
    const int tx  = tid & 15;
    const int ty  = tid >> 4;

    const int ar = tid >> 2, ac = (tid & 3) * 2;
    const int wr = tid >> 1, wc = (tid & 1) * 4;

    const float* Ap = A + (size_t)(bm + ar) * K + ac;
    const float* Wp = W + (size_t)(bn + wr) * K + wc;

    float acc[4][8];
#pragma unroll
    for (int i = 0; i < 4; i++)
#pragma unroll
        for (int j = 0; j < 8; j++) acc[i][j] = 0.0f;

    float2 a = *reinterpret_cast<const float2*>(Ap);
    float4 w = *reinterpret_cast<const float4*>(Wp);
    As[0][ac+0][ar] = a.x; As[0][ac+1][ar] = a.y;
    Ws[0][wc+0][wr] = w.x; Ws[0][wc+1][wr] = w.y;
    Ws[0][wc+2][wr] = w.z; Ws[0][wc+3][wr] = w.w;
    __syncthreads();

    const int nk = K >> 3;
    for (int it = 0; it < nk; it++) {
        const int cur = it & 1, nxt = cur ^ 1;
        if (it + 1 < nk) {
            a = *reinterpret_cast<const float2*>(Ap + (it + 1) * 8);
            w = *reinterpret_cast<const float4*>(Wp + (it + 1) * 8);
        }
#pragma unroll
        for (int kk = 0; kk < 8; kk++) {
            float af[4], wf[8];
            *reinterpret_cast<float4*>(af)     = *reinterpret_cast<const float4*>(&As[cur][kk][ty*4]);
            *reinterpret_cast<float4*>(wf)     = *reinterpret_cast<const float4*>(&Ws[cur][kk][tx*8]);
            *reinterpret_cast<float4*>(wf + 4) = *reinterpret_cast<const float4*>(&Ws[cur][kk][tx*8+4]);
#pragma unroll
            for (int i = 0; i < 4; i++)
#pragma unroll
                for (int j = 0; j < 8; j++) acc[i][j] += af[i] * wf[j];
        }
        if (it + 1 < nk) {
            As[nxt][ac+0][ar] = a.x; As[nxt][ac+1][ar] = a.y;
            Ws[nxt][wc+0][wr] = w.x; Ws[nxt][wc+1][wr] = w.y;
            Ws[nxt][wc+2][wr] = w.z; Ws[nxt][wc+3][wr] = w.w;
        }
        __syncthreads();
    }

#pragma unroll
    for (int i = 0; i < 4; i++) {
        const int row = bm + ty * 4 + i;
        const float* bp = bias + bn + tx * 8;
        float* cp = C + (size_t)row * Nout + bn + tx * 8;
        float4 b0 = *reinterpret_cast<const float4*>(bp);
        float4 b1 = *reinterpret_cast<const float4*>(bp + 4);
        float4 o0 = {acc[i][0]+b0.x, acc[i][1]+b0.y, acc[i][2]+b0.z, acc[i][3]+b0.w};
        float4 o1 = {acc[i][4]+b1.x, acc[i][5]+b1.y, acc[i][6]+b1.z, acc[i][7]+b1.w};
        *reinterpret_cast<float4*>(cp)     = o0;
        *reinterpret_cast<float4*>(cp + 4) = o1;
    }
}

// ---------------------------------------------------------------------------
// Scores + Pos_Sampling + softmax -> g_w. One CTA per (b, n).
// ---------------------------------------------------------------------------
__global__ __launch_bounds__(256) void score_kernel(
    const float* __restrict__ Kb,   // (SH, DH)
    const float* __restrict__ Sk,   // (NH, KC, KC)
    const float* __restrict__ Sb)   // (NH, KC)
{
    const int n   = blockIdx.x;
    const int b   = blockIdx.y;
    const int tid = threadIdx.x;

    __shared__ float sq [SH * DH];
    __shared__ float ssc[SH * KC];
    __shared__ float shs[NH * KC];

    const float* qrow = g_qproj + (size_t)(b * N_ + n) * (SH * DH);
    for (int i = tid; i < SH * DH; i += 256) sq[i] = qrow[i];
    __syncthreads();

    if (tid < SH * KC) {
        const int s   = tid / KC;
        const int k   = tid % KC;
        const int dil = c_dil[s];
        const int pl  = ((KC - 1) * dil) >> 1;
        const int idx = n + k * dil - pl;
        const float* krow = (idx >= 0 && idx < N_)
            ? (g_kproj + (size_t)(b * N_ + idx) * (SH * DH) + s * DH)
            : (Kb + s * DH);
        const float4* k4 = reinterpret_cast<const float4*>(krow);
        const float4* q4 = reinterpret_cast<const float4*>(sq + s * DH);
        float acc = 0.0f;
#pragma unroll 8
        for (int d = 0; d < DH / 4; d++) {
            float4 kv = k4[d];
            float4 qv = q4[d];
            acc += qv.x * kv.x + qv.y * kv.y + qv.z * kv.z + qv.w * kv.w;
        }
        ssc[tid] = acc;
    }
    __syncthreads();

    for (int t = tid; t < NH * KC; t += 256) {
        const int h = t / KC;
        const int j = t % KC;
        const int s = c_sub[h];
        const float* skrow = Sk + ((size_t)h * KC + j) * KC;
        const float* scrow = ssc + s * KC;
        float acc = Sb[h * KC + j];
#pragma unroll
        for (int k = 0; k < KC; k++) acc += scrow[k] * skrow[k];
        shs[t] = acc;
    }
    __syncthreads();

    if (tid < NH) {
        float* row = shs + tid * KC;
        float m = row[0];
#pragma unroll
        for (int j = 1; j < KC; j++) m = fmaxf(m, row[j]);
        float sum = 0.0f;
#pragma unroll
        for (int j = 0; j < KC; j++) { float e = expf(row[j] - m); row[j] = e; sum += e; }
        const float inv = 1.0f / sum;
#pragma unroll
        for (int j = 0; j < KC; j++) row[j] *= inv;
    }
    __syncthreads();

    float* wout = g_w + (size_t)(b * N_ + n) * (NH * KC);
    for (int t = tid; t < NH * KC; t += 256) wout[t] = shs[t];
}

// ---------------------------------------------------------------------------
// Weighted V gather with residue-class tiling.
// For dilation d, all taps of n lie on residue class (n - pl) mod d, so a
// tile of 32 n's sharing a residue needs only 63 rows -> 32 KB smem tile.
// Grid: (32 tiles, NH, B). 128 threads.
// ---------------------------------------------------------------------------
__global__ __launch_bounds__(128) void apply_kernel(
    const float* __restrict__ Vb)   // (NH, DH)
{
    const int z   = blockIdx.x;     // tile id in [0,32)
    const int h   = blockIdx.y;
    const int b   = blockIdx.z;
    const int tid = threadIdx.x;

    const int d   = c_dilh[h];
    const int pl  = ((KC - 1) * d) >> 1;
    const int cpr = 32 / d;          // chunks per residue
    const int r0  = z / cpr;         // residue class
    const int c0  = z % cpr;         // chunk within residue
    const int n0  = r0 + c0 * 32 * d;   // n(t) = n0 + t*d
    const int base = n0 - pl;            // row(u) = base + u*d, u in [0,63]

    __shared__ float vt[63][DH];
    __shared__ float wt[32][KC];

    const float vb = Vb[h * DH + tid];

    // load 63 V rows (strided by d) into smem
    const float* vsrc = g_vproj + ((size_t)b * N_) * (NH * DH) + h * DH + tid;
#pragma unroll 1
    for (int u = 0; u < 63; u++) {
        const int idx = base + u * d;
        vt[u][tid] = (idx >= 0 && idx < N_) ? vsrc[(size_t)idx * (NH * DH)] : vb;
    }
    // load weight tile
    const float* wsrc = g_w + ((size_t)b * N_) * (NH * KC) + h * KC;
#pragma unroll
    for (int i = tid; i < 32 * KC; i += 128) {
        const int t = i >> 5, j = i & 31;
        wt[t][j] = wsrc[(size_t)(n0 + t * d) * (NH * KC) + j];
    }
    __syncthreads();

    // compute: 4 thread-groups over t, 32 lanes x float4 over d
    const int dq = (tid & 31) * 4;
    const int tq = tid >> 5;
    float* aout = g_attn + ((size_t)b * N_) * (NH * DH) + h * DH + dq;
#pragma unroll
    for (int t8 = 0; t8 < 8; t8++) {
        const int t = tq + t8 * 4;
        float4 acc = {0.f, 0.f, 0.f, 0.f};
#pragma unroll
        for (int j = 0; j < KC; j++) {
            const float wv = wt[t][j];
            const float4 v = *reinterpret_cast<const float4*>(&vt[t + j][dq]);
            acc.x += wv * v.x; acc.y += wv * v.y;
            acc.z += wv * v.z; acc.w += wv * v.w;
        }
        *reinterpret_cast<float4*>(aout + (size_t)(n0 + t * d) * (NH * DH)) = acc;
    }
}

extern "C" void kernel_launch(void* const* d_in, const int* in_sizes, int n_in,
                              void* d_out, int out_size)
{
    const float* query = (const float*)d_in[0];
    const float* key   = (const float*)d_in[1];
    const float* value = (const float*)d_in[2];
    const float* Qk    = (const float*)d_in[3];
    const float* Qb    = (const float*)d_in[4];
    const float* Kk    = (const float*)d_in[5];
    const float* Kb    = (const float*)d_in[6];
    const float* Vk    = (const float*)d_in[7];
    const float* Vb    = (const float*)d_in[8];
    const float* Sk    = (const float*)d_in[9];
    const float* Sb    = (const float*)d_in[10];
    const float* Ck    = (const float*)d_in[11];
    const float* Cb    = (const float*)d_in[12];
    float* out = (float*)d_out;

    float *qp = nullptr, *kp = nullptr, *vp = nullptr, *ap = nullptr;
    cudaGetSymbolAddress((void**)&qp, g_qproj);
    cudaGetSymbolAddress((void**)&kp, g_kproj);
    cudaGetSymbolAddress((void**)&vp, g_vproj);
    cudaGetSymbolAddress((void**)&ap, g_attn);

    const int M = B_ * N_;  // 2048

    // Q / K projections: (2048,640)x(640,640)^T, 64x128 tiles -> 160 CTAs each
    {
        dim3 grid(DM / 128, M / 64);
        gemm64_kernel<<<grid, 256>>>(query, Qk, Qb, qp, M, SH * DH, DM);
        gemm64_kernel<<<grid, 256>>>(key,   Kk, Kb, kp, M, SH * DH, DM);
    }
    // V projection: (2048,1792), 128x128 tiles -> 224 CTAs
    {
        dim3 grid((NH * DH) / 128, M / 128);
        gemm128_kernel<<<grid, 256>>>(value, Vk, Vb, vp, M, NH * DH, DM);
    }
    // scores -> softmax weights
    {
        dim3 grid(N_, B_);
        score_kernel<<<grid, 256>>>(Kb, Sk, Sb);
    }
    // weighted V gather
    {
        dim3 grid(32, NH, B_);
        apply_kernel<<<grid, 128>>>(Vb);
    }
    // Collapse: (2048,640) = (2048,1792)x(640,1792)^T, 64x128 -> 160 CTAs
    {
        dim3 grid(DM / 128, M / 64);
        gemm64_kernel<<<grid, 256>>>(ap, Ck, Cb, out, M, DM, NH * DH);
    }
}

// round 3
// speedup vs baseline: 1.6766x; 1.6766x over previous
#include <cuda_runtime.h>
#include <cuda_bf16.h>
#include <cstdint>

#define B_   2
#define N_   1024
#define DM   640
#define SH   5
#define DH   128
#define NH   14
#define KC   32
#define VW   (NH * DH)        // 1792

// -------- device scratch (no allocation allowed) --------
__device__ float g_qproj[B_ * N_ * SH * DH];
__device__ float g_kproj[B_ * N_ * SH * DH];
__device__ float g_vproj[B_ * N_ * NH * DH];
__device__ float g_attn [B_ * N_ * NH * DH];
__device__ float g_part [2 * B_ * N_ * DM];    // split-K partials for collapse

__constant__ int c_dil  [SH] = {1, 1, 2, 4, 8};
__constant__ int c_hbase[SH] = {0, 5, 10, 12, 13};
__constant__ int c_hcnt [SH] = {5, 5, 2, 1, 1};

// ---------------------------------------------------------------------------
// Double-buffered SGEMM body: 128x128 tile, BK=8, 256 threads, 8x8 microtile.
// C[m,o] = sum_d A[m,d]*W[o,d] (+ bias[o] if bias).  Row strides lda/ldw/Nout.
// ---------------------------------------------------------------------------
__device__ __forceinline__ void gemm128_body(
    const float* __restrict__ A, const float* __restrict__ W,
    const float* __restrict__ bias, float* __restrict__ C,
    int Nout, int Klen, int lda, int ldw)
{
    __shared__ float As[2][8][128];
    __shared__ float Ws[2][8][128];

    const int bm  = blockIdx.y * 128;
    const int bn  = blockIdx.x * 128;
    const int tid = threadIdx.x;
    const int tx  = tid & 15;
    const int ty  = tid >> 4;
    const int lr  = tid >> 1;
    const int lc  = (tid & 1) * 4;

    const float* Ap = A + (size_t)(bm + lr) * lda + lc;
    const float* Wp = W + (size_t)(bn + lr) * ldw + lc;

    float acc[8][8];
#pragma unroll
    for (int i = 0; i < 8; i++)
#pragma unroll
        for (int j = 0; j < 8; j++) acc[i][j] = 0.0f;

    float4 a = *reinterpret_cast<const float4*>(Ap);
    float4 w = *reinterpret_cast<const float4*>(Wp);
    As[0][lc+0][lr] = a.x; As[0][lc+1][lr] = a.y;
    As[0][lc+2][lr] = a.z; As[0][lc+3][lr] = a.w;
    Ws[0][lc+0][lr] = w.x; Ws[0][lc+1][lr] = w.y;
    Ws[0][lc+2][lr] = w.z; Ws[0][lc+3][lr] = w.w;
    __syncthreads();

    const int nk = Klen >> 3;
    for (int it = 0; it < nk; it++) {
        const int cur = it & 1, nxt = cur ^ 1;
        if (it + 1 < nk) {
            a = *reinterpret_cast<const float4*>(Ap + (it + 1) * 8);
            w = *reinterpret_cast<const float4*>(Wp + (it + 1) * 8);
        }
#pragma unroll
        for (int kk = 0; kk < 8; kk++) {
            float af[8], wf[8];
            *reinterpret_cast<float4*>(af)     = *reinterpret_cast<const float4*>(&As[cur][kk][ty*8]);
            *reinterpret_cast<float4*>(af + 4) = *reinterpret_cast<const float4*>(&As[cur][kk][ty*8+4]);
            *reinterpret_cast<float4*>(wf)     = *reinterpret_cast<const float4*>(&Ws[cur][kk][tx*8]);
            *reinterpret_cast<float4*>(wf + 4) = *reinterpret_cast<const float4*>(&Ws[cur][kk][tx*8+4]);
#pragma unroll
            for (int i = 0; i < 8; i++)
#pragma unroll
                for (int j = 0; j < 8; j++) acc[i][j] += af[i] * wf[j];
        }
        if (it + 1 < nk) {
            As[nxt][lc+0][lr] = a.x; As[nxt][lc+1][lr] = a.y;
            As[nxt][lc+2][lr] = a.z; As[nxt][lc+3][lr] = a.w;
            Ws[nxt][lc+0][lr] = w.x; Ws[nxt][lc+1][lr] = w.y;
            Ws[nxt][lc+2][lr] = w.z; Ws[nxt][lc+3][lr] = w.w;
        }
        __syncthreads();
    }

#pragma unroll
    for (int i = 0; i < 8; i++) {
        const int row = bm + ty * 8 + i;
        float* cp = C + (size_t)row * Nout + bn + tx * 8;
        float4 b0 = {0.f,0.f,0.f,0.f}, b1 = {0.f,0.f,0.f,0.f};
        if (bias) {
            b0 = *reinterpret_cast<const float4*>(bias + bn + tx * 8);
            b1 = *reinterpret_cast<const float4*>(bias + bn + tx * 8 + 4);
        }
        float4 o0 = {acc[i][0]+b0.x, acc[i][1]+b0.y, acc[i][2]+b0.z, acc[i][3]+b0.w};
        float4 o1 = {acc[i][4]+b1.x, acc[i][5]+b1.y, acc[i][6]+b1.z, acc[i][7]+b1.w};
        *reinterpret_cast<float4*>(cp)     = o0;
        *reinterpret_cast<float4*>(cp + 4) = o1;
    }
}

// Q + K projections batched over blockIdx.z (160 CTAs total).
__global__ __launch_bounds__(256) void gemm_qk_kernel(
    const float* __restrict__ q,  const float* __restrict__ k,
    const float* __restrict__ Qk, const float* __restrict__ Kk,
    const float* __restrict__ Qb, const float* __restrict__ Kb,
    float* __restrict__ qo, float* __restrict__ ko)
{
    const int z = blockIdx.z;
    const float* A    = z ? k  : q;
    const float* W    = z ? Kk : Qk;
    const float* bias = z ? Kb : Qb;
    float*       C    = z ? ko : qo;
    gemm128_body(A, W, bias, C, SH * DH, DM, DM, DM);
}

// V projection (224 CTAs).
__global__ __launch_bounds__(256) void gemm_v_kernel(
    const float* __restrict__ v, const float* __restrict__ Vk,
    const float* __restrict__ Vb, float* __restrict__ vo)
{
    gemm128_body(v, Vk, Vb, vo, VW, DM, DM, DM);
}

// Collapse with split-K=2 batched over blockIdx.z (160 CTAs).
__global__ __launch_bounds__(256) void gemm_col_kernel(
    const float* __restrict__ Ck, float* __restrict__ part)
{
    const int z = blockIdx.z;
    const int koff = z * (VW / 2);
    gemm128_body(g_attn + koff, Ck + koff, nullptr,
                 part + (size_t)z * (B_ * N_ * DM),
                 DM, VW / 2, VW, VW);
}

// out = part0 + part1 + Cb
__global__ __launch_bounds__(256) void add_bias_kernel(
    const float* __restrict__ part, const float* __restrict__ Cb,
    float* __restrict__ out)
{
    const int i = blockIdx.x * 256 + threadIdx.x;     // float4 index
    const float4 p0 = reinterpret_cast<const float4*>(part)[i];
    const float4 p1 = reinterpret_cast<const float4*>(part + (size_t)B_*N_*DM)[i];
    const float4 bb = reinterpret_cast<const float4*>(Cb)[i % (DM/4)];
    float4 o = {p0.x+p1.x+bb.x, p0.y+p1.y+bb.y, p0.z+p1.z+bb.z, p0.w+p1.w+bb.w};
    reinterpret_cast<float4*>(out)[i] = o;
}

// ---------------------------------------------------------------------------
// Fused banded attention with residue-class tiling.
// Grid (32 tiles, SH, B), 256 threads.
// For dilation d, taps of 32 same-residue n's span 63 band rows -> smem tile.
// Phase 1: scores via warp-cooperative dots (shuffle reduce).
// Phase 2 per head: Pos_Sampling linear -> softmax -> V-apply (reuses tile).
// ---------------------------------------------------------------------------
__global__ __launch_bounds__(256) void attn_fused_kernel(
    const float* __restrict__ Kb,   // (SH, DH)
    const float* __restrict__ Vb,   // (NH, DH)
    const float* __restrict__ Sk,   // (NH, KC, KC)
    const float* __restrict__ Sb)   // (NH, KC)
{
    const int z   = blockIdx.x;
    const int s   = blockIdx.y;
    const int b   = blockIdx.z;
    const int tid = threadIdx.x;
    const int lane = tid & 31;
    const int wrp  = tid >> 5;

    const int dil = c_dil[s];
    const int pl  = ((KC - 1) * dil) >> 1;
    const int cpr = 32 / dil;
    const int r0  = z / cpr;
    const int c0  = z % cpr;
    const int n0  = r0 + c0 * 32 * dil;   // n(t) = n0 + t*dil
    const int base = n0 - pl;             // band row(u) = base + u*dil

    __shared__ float kv [63][DH];      // K tile, later reused as V tile
    __shared__ float ssc[32][33];      // subhead scores (padded)
    __shared__ float sks[32][32];      // Sk[h] tile
    __shared__ float shs[32][33];      // head scores -> weights (padded)

    // ---- load K band tile ----
    for (int i = tid; i < 63 * DH; i += 256) {
        const int u = i >> 7, col = i & 127;
        const int idx = base + u * dil;
        kv[u][col] = (idx >= 0 && idx < N_)
            ? g_kproj[(size_t)(b * N_ + idx) * (SH * DH) + s * DH + col]
            : Kb[s * DH + col];
    }
    __syncthreads();

    // ---- scores: warp w handles t = w, w+8, w+16, w+24 ----
#pragma unroll
    for (int ti = 0; ti < 4; ti++) {
        const int t  = wrp + ti * 8;
        const int nt = n0 + t * dil;
        const float4 ql = *reinterpret_cast<const float4*>(
            g_qproj + (size_t)(b * N_ + nt) * (SH * DH) + s * DH + lane * 4);
#pragma unroll
        for (int k = 0; k < KC; k++) {
            const float4 kf = *reinterpret_cast<const float4*>(&kv[t + k][lane * 4]);
            float p = ql.x*kf.x + ql.y*kf.y + ql.z*kf.z + ql.w*kf.w;
            p += __shfl_xor_sync(0xffffffffu, p, 16);
            p += __shfl_xor_sync(0xffffffffu, p, 8);
            p += __shfl_xor_sync(0xffffffffu, p, 4);
            p += __shfl_xor_sync(0xffffffffu, p, 2);
            p += __shfl_xor_sync(0xffffffffu, p, 1);
            if (lane == 0) ssc[t][k] = p;
        }
    }
    __syncthreads();

    // ---- per-head: Pos_Sampling -> softmax -> apply ----
    const int hcnt = c_hcnt[s];
    for (int hi = 0; hi < hcnt; hi++) {
        const int h = c_hbase[s] + hi;

        // load Sk[h] (32x32)
        for (int i = tid; i < KC * KC; i += 256)
            sks[i >> 5][i & 31] = Sk[(size_t)h * KC * KC + i];
        __syncthreads();

        // head scores: shs[t][j] = Sb[h,j] + sum_k ssc[t][k]*sks[j][k]
        for (int i = tid; i < 32 * KC; i += 256) {
            const int t = i & 31, j = i >> 5;
            float acc = Sb[h * KC + j];
#pragma unroll
            for (int k = 0; k < KC; k++) acc += ssc[t][k] * sks[j][k];
            shs[t][j] = acc;
        }
        __syncthreads();

        // softmax per row
        if (tid < 32) {
            float* row = shs[tid];
            float m = row[0];
#pragma unroll
            for (int j = 1; j < KC; j++) m = fmaxf(m, row[j]);
            float sum = 0.0f;
#pragma unroll
            for (int j = 0; j < KC; j++) { float e = expf(row[j]-m); row[j] = e; sum += e; }
            const float inv = 1.0f / sum;
#pragma unroll
            for (int j = 0; j < KC; j++) row[j] *= inv;
        }
        __syncthreads();

        // load V band tile for head h (reuse kv buffer)
        for (int i = tid; i < 63 * DH; i += 256) {
            const int u = i >> 7, col = i & 127;
            const int idx = base + u * dil;
            kv[u][col] = (idx >= 0 && idx < N_)
                ? g_vproj[(size_t)(b * N_ + idx) * VW + h * DH + col]
                : Vb[h * DH + col];
        }
        __syncthreads();

        // apply: thread (grp=tid>>5, dq=lane*4) over t = grp + tt*8
        const int dq = lane * 4;
#pragma unroll
        for (int tt = 0; tt < 4; tt++) {
            const int t  = wrp + tt * 8;
            const int nt = n0 + t * dil;
            float4 acc = {0.f, 0.f, 0.f, 0.f};
#pragma unroll
            for (int j = 0; j < KC; j++) {
                const float wv = shs[t][j];
                const float4 v = *reinterpret_cast<const float4*>(&kv[t + j][dq]);
                acc.x += wv * v.x; acc.y += wv * v.y;
                acc.z += wv * v.z; acc.w += wv * v.w;
            }
            *reinterpret_cast<float4*>(
                g_attn + (size_t)(b * N_ + nt) * VW + h * DH + dq) = acc;
        }
        __syncthreads();   // before overwriting sks/shs/kv next head
    }
}

extern "C" void kernel_launch(void* const* d_in, const int* in_sizes, int n_in,
                              void* d_out, int out_size)
{
    const float* query = (const float*)d_in[0];
    const float* key   = (const float*)d_in[1];
    const float* value = (const float*)d_in[2];
    const float* Qk    = (const float*)d_in[3];
    const float* Qb    = (const float*)d_in[4];
    const float* Kk    = (const float*)d_in[5];
    const float* Kb    = (const float*)d_in[6];
    const float* Vk    = (const float*)d_in[7];
    const float* Vb    = (const float*)d_in[8];
    const float* Sk    = (const float*)d_in[9];
    const float* Sb    = (const float*)d_in[10];
    const float* Ck    = (const float*)d_in[11];
    const float* Cb    = (const float*)d_in[12];
    float* out = (float*)d_out;

    float *qp = nullptr, *kp = nullptr, *vp = nullptr, *pp = nullptr;
    cudaGetSymbolAddress((void**)&qp, g_qproj);
    cudaGetSymbolAddress((void**)&kp, g_kproj);
    cudaGetSymbolAddress((void**)&vp, g_vproj);
    cudaGetSymbolAddress((void**)&pp, g_part);

    const int M = B_ * N_;  // 2048

    // Q + K projections batched: grid (5, 16, 2) = 160 CTAs
    {
        dim3 grid(DM / 128, M / 128, 2);
        gemm_qk_kernel<<<grid, 256>>>(query, key, Qk, Kk, Qb, Kb, qp, kp);
    }
    // V projection: grid (14, 16) = 224 CTAs
    {
        dim3 grid(VW / 128, M / 128);
        gemm_v_kernel<<<grid, 256>>>(value, Vk, Vb, vp);
    }
    // fused banded attention
    {
        dim3 grid(32, SH, B_);
        attn_fused_kernel<<<grid, 256>>>(Kb, Vb, Sk, Sb);
    }
    // collapse split-K=2: grid (5, 16, 2) = 160 CTAs
    {
        dim3 grid(DM / 128, M / 128, 2);
        gemm_col_kernel<<<grid, 256>>>(Ck, pp);
    }
    // sum partials + bias
    {
        add_bias_kernel<<<(M * DM / 4) / 256, 256>>>(pp, Cb, out);
    }
}

// round 4
// speedup vs baseline: 2.9195x; 1.7413x over previous
#include <cuda_runtime.h>
#include <cuda_bf16.h>
#include <cstdint>

#define B_   2
#define N_   1024
#define DM   640
#define SH   5
#define DH   128
#define NH   14
#define KC   32
#define VW   (NH * DH)        // 1792
#define KE_P (3 * DM)         // 1920  expanded K for projections
#define KE_C (3 * VW)         // 5376  expanded K for collapse

// -------- fp32 device scratch --------
__device__ float g_qproj[B_ * N_ * SH * DH];
__device__ float g_kproj[B_ * N_ * SH * DH];
__device__ float g_vproj[B_ * N_ * NH * DH];
__device__ float g_attn [B_ * N_ * NH * DH];
__device__ float g_part [2 * B_ * N_ * DM];

// -------- bf16x3-expanded operands --------
__device__ __nv_bfloat16 gb_q [B_ * N_ * KE_P];
__device__ __nv_bfloat16 gb_k [B_ * N_ * KE_P];
__device__ __nv_bfloat16 gb_v [B_ * N_ * KE_P];
__device__ __nv_bfloat16 gb_Qk[(SH * DH) * KE_P];
__device__ __nv_bfloat16 gb_Kk[(SH * DH) * KE_P];
__device__ __nv_bfloat16 gb_Vk[VW * KE_P];
__device__ __nv_bfloat16 gb_Ck[DM * KE_C];
__device__ __nv_bfloat16 gb_at[B_ * N_ * KE_C];

__constant__ int c_dil  [SH] = {1, 1, 2, 4, 8};
__constant__ int c_hbase[SH] = {0, 5, 10, 12, 13};
__constant__ int c_hcnt [SH] = {5, 5, 2, 1, 1};

// ---------------------------------------------------------------------------
// fp32 -> bf16x3 expansion.  mode 0 (activations): row = [hi | hi | lo]
//                            mode 1 (weights):     row = [hi | lo | hi]
// Dot(actRow, wRow) over 3K = hi*hi + hi*lo + lo*hi  (~fp32 precision).
// ---------------------------------------------------------------------------
__global__ __launch_bounds__(256) void cvt_kernel(
    const float* __restrict__ in, __nv_bfloat16* __restrict__ out,
    int total_pairs, int K, int mode)
{
    const int i = blockIdx.x * 256 + threadIdx.x;
    if (i >= total_pairs) return;
    const float2 x = reinterpret_cast<const float2*>(in)[i];
    const __nv_bfloat16 h0 = __float2bfloat16(x.x);
    const __nv_bfloat16 h1 = __float2bfloat16(x.y);
    const __nv_bfloat16 l0 = __float2bfloat16(x.x - __bfloat162float(h0));
    const __nv_bfloat16 l1 = __float2bfloat16(x.y - __bfloat162float(h1));
    __nv_bfloat162 hh; hh.x = h0; hh.y = h1;
    __nv_bfloat162 ll; ll.x = l0; ll.y = l1;
    const int k2 = K >> 1;
    const int r = i / k2, k = i % k2;
    __nv_bfloat162* orow = reinterpret_cast<__nv_bfloat162*>(out + (size_t)r * 3 * K);
    if (mode == 0) {
        orow[k] = hh; orow[k2 + k] = hh; orow[2 * k2 + k] = ll;
    } else {
        orow[k] = hh; orow[k2 + k] = ll; orow[2 * k2 + k] = hh;
    }
}

// ---------------------------------------------------------------------------
// bf16 tensor-core GEMM: C[m,o] = sum_k A[m,k]*W[o,k] (+bias[o])
// 128x128 tile, BK=32, 256 threads (8 warps, 2x4), warp tile 64x32,
// mma.sync.m16n8k16 bf16 -> fp32, double-buffered smem.
// ---------------------------------------------------------------------------
__device__ __forceinline__ uint32_t smem_u32(const void* p) {
    return (uint32_t)__cvta_generic_to_shared(p);
}
__device__ __forceinline__ void ldmx4(uint32_t& r0, uint32_t& r1,
                                      uint32_t& r2, uint32_t& r3, uint32_t a) {
    asm volatile("ldmatrix.sync.aligned.m8n8.x4.shared.b16 {%0,%1,%2,%3}, [%4];"
        : "=r"(r0), "=r"(r1), "=r"(r2), "=r"(r3) : "r"(a));
}
__device__ __forceinline__ void mma16816(float* d, const uint32_t* a,
                                         const uint32_t b0, const uint32_t b1) {
    asm volatile(
        "mma.sync.aligned.m16n8k16.row.col.f32.bf16.bf16.f32 "
        "{%0,%1,%2,%3}, {%4,%5,%6,%7}, {%8,%9}, {%0,%1,%2,%3};"
        : "+f"(d[0]), "+f"(d[1]), "+f"(d[2]), "+f"(d[3])
        : "r"(a[0]), "r"(a[1]), "r"(a[2]), "r"(a[3]), "r"(b0), "r"(b1));
}

#define BKT 32
#define SPAD 8   // bf16 pad -> row stride 40 (80B, conflict-free ldmatrix)

__device__ __forceinline__ void mma_gemm_body(
    const __nv_bfloat16* __restrict__ A,   // (M x Klen) row-major, lda
    const __nv_bfloat16* __restrict__ W,   // (Nout x Klen) row-major, ldw
    const float* __restrict__ bias,
    float* __restrict__ C, int Klen, int lda, int ldw, int ldc)
{
    __shared__ __align__(16) __nv_bfloat16 As[2][128][BKT + SPAD];
    __shared__ __align__(16) __nv_bfloat16 Bs[2][128][BKT + SPAD];

    const int bm = blockIdx.y * 128;
    const int bn = blockIdx.x * 128;
    const int tid = threadIdx.x;
    const int lane = tid & 31, wid = tid >> 5;
    const int wm = (wid & 1) * 64;
    const int wn = (wid >> 1) * 32;

    const int gr = tid >> 2;
    const int gc = (tid & 3) * 8;

    const __nv_bfloat16* Ap = A + (size_t)(bm + gr) * lda + gc;
    const __nv_bfloat16* Wp = W + (size_t)(bn + gr) * ldw + gc;

    float acc[4][4][4] = {};

    uint4 a0 = *reinterpret_cast<const uint4*>(Ap);
    uint4 a1 = *reinterpret_cast<const uint4*>(Ap + (size_t)64 * lda);
    uint4 w0 = *reinterpret_cast<const uint4*>(Wp);
    uint4 w1 = *reinterpret_cast<const uint4*>(Wp + (size_t)64 * ldw);
    *reinterpret_cast<uint4*>(&As[0][gr     ][gc]) = a0;
    *reinterpret_cast<uint4*>(&As[0][gr + 64][gc]) = a1;
    *reinterpret_cast<uint4*>(&Bs[0][gr     ][gc]) = w0;
    *reinterpret_cast<uint4*>(&Bs[0][gr + 64][gc]) = w1;
    __syncthreads();

    // ldmatrix lane addressing
    const int a_row = wm + (lane & 15);
    const int a_kof = (lane >> 4) * 8;
    const int b_row = wn + (lane & 7) + (lane >> 4) * 8;
    const int b_kof = ((lane >> 3) & 1) * 8;

    const int nk = Klen / BKT;
    for (int it = 0; it < nk; ++it) {
        const int cur = it & 1, nxt = cur ^ 1;
        if (it + 1 < nk) {
            const __nv_bfloat16* An = Ap + (it + 1) * BKT;
            const __nv_bfloat16* Wn = Wp + (it + 1) * BKT;
            a0 = *reinterpret_cast<const uint4*>(An);
            a1 = *reinterpret_cast<const uint4*>(An + (size_t)64 * lda);
            w0 = *reinterpret_cast<const uint4*>(Wn);
            w1 = *reinterpret_cast<const uint4*>(Wn + (size_t)64 * ldw);
        }
#pragma unroll
        for (int ks = 0; ks < 2; ++ks) {
            const int k0 = ks * 16;
            uint32_t af[4][4], bf[2][4];
#pragma unroll
            for (int mi = 0; mi < 4; mi++)
                ldmx4(af[mi][0], af[mi][1], af[mi][2], af[mi][3],
                      smem_u32(&As[cur][a_row + mi * 16][k0 + a_kof]));
#pragma unroll
            for (int g = 0; g < 2; g++)
                ldmx4(bf[g][0], bf[g][1], bf[g][2], bf[g][3],
                      smem_u32(&Bs[cur][b_row + g * 16][k0 + b_kof]));
#pragma unroll
            for (int mi = 0; mi < 4; mi++)
#pragma unroll
                for (int ni = 0; ni < 4; ni++)
                    mma16816(acc[mi][ni], af[mi],
                             bf[ni >> 1][(ni & 1) * 2], bf[ni >> 1][(ni & 1) * 2 + 1]);
        }
        if (it + 1 < nk) {
            *reinterpret_cast<uint4*>(&As[nxt][gr     ][gc]) = a0;
            *reinterpret_cast<uint4*>(&As[nxt][gr + 64][gc]) = a1;
            *reinterpret_cast<uint4*>(&Bs[nxt][gr     ][gc]) = w0;
            *reinterpret_cast<uint4*>(&Bs[nxt][gr + 64][gc]) = w1;
        }
        __syncthreads();
    }

    const int g = lane >> 2, t = lane & 3;
#pragma unroll
    for (int mi = 0; mi < 4; mi++) {
        const int row0 = bm + wm + mi * 16 + g;
#pragma unroll
        for (int ni = 0; ni < 4; ni++) {
            const int col = bn + wn + ni * 8 + t * 2;
            float b0 = 0.f, b1 = 0.f;
            if (bias) { b0 = bias[col]; b1 = bias[col + 1]; }
            float2 v0 = {acc[mi][ni][0] + b0, acc[mi][ni][1] + b1};
            float2 v1 = {acc[mi][ni][2] + b0, acc[mi][ni][3] + b1};
            *reinterpret_cast<float2*>(&C[(size_t)row0 * ldc + col]) = v0;
            *reinterpret_cast<float2*>(&C[(size_t)(row0 + 8) * ldc + col]) = v1;
        }
    }
}

__global__ __launch_bounds__(256) void mma_qk_kernel(
    const float* __restrict__ Qb, const float* __restrict__ Kb)
{
    if (blockIdx.z == 0)
        mma_gemm_body(gb_q, gb_Qk, Qb, g_qproj, KE_P, KE_P, KE_P, SH * DH);
    else
        mma_gemm_body(gb_k, gb_Kk, Kb, g_kproj, KE_P, KE_P, KE_P, SH * DH);
}

__global__ __launch_bounds__(256) void mma_v_kernel(const float* __restrict__ Vb)
{
    mma_gemm_body(gb_v, gb_Vk, Vb, g_vproj, KE_P, KE_P, KE_P, VW);
}

__global__ __launch_bounds__(256) void mma_col_kernel()
{
    const int z = blockIdx.z;
    const int koff = z * (KE_C / 2);
    mma_gemm_body(gb_at + koff, gb_Ck + koff, nullptr,
                  g_part + (size_t)z * (B_ * N_ * DM),
                  KE_C / 2, KE_C, KE_C, DM);
}

// out = part0 + part1 + Cb
__global__ __launch_bounds__(256) void add_bias_kernel(
    const float* __restrict__ Cb, float* __restrict__ out)
{
    const int i = blockIdx.x * 256 + threadIdx.x;
    const float4 p0 = reinterpret_cast<const float4*>(g_part)[i];
    const float4 p1 = reinterpret_cast<const float4*>(g_part + (size_t)B_ * N_ * DM)[i];
    const float4 bb = reinterpret_cast<const float4*>(Cb)[i % (DM / 4)];
    float4 o = {p0.x + p1.x + bb.x, p0.y + p1.y + bb.y,
                p0.z + p1.z + bb.z, p0.w + p1.w + bb.w};
    reinterpret_cast<float4*>(out)[i] = o;
}

// ---------------------------------------------------------------------------
// Fused banded attention (unchanged from round 3 — passing, ~tile-reuse bound)
// ---------------------------------------------------------------------------
__global__ __launch_bounds__(256) void attn_fused_kernel(
    const float* __restrict__ Kb, const float* __restrict__ Vb,
    const float* __restrict__ Sk, const float* __restrict__ Sb)
{
    const int z   = blockIdx.x;
    const int s   = blockIdx.y;
    const int b   = blockIdx.z;
    const int tid = threadIdx.x;
    const int lane = tid & 31;
    const int wrp  = tid >> 5;

    const int dil = c_dil[s];
    const int pl  = ((KC - 1) * dil) >> 1;
    const int cpr = 32 / dil;
    const int r0  = z / cpr;
    const int c0  = z % cpr;
    const int n0  = r0 + c0 * 32 * dil;
    const int base = n0 - pl;

    __shared__ float kv [63][DH];
    __shared__ float ssc[32][33];
    __shared__ float sks[32][32];
    __shared__ float shs[32][33];

    for (int i = tid; i < 63 * DH; i += 256) {
        const int u = i >> 7, col = i & 127;
        const int idx = base + u * dil;
        kv[u][col] = (idx >= 0 && idx < N_)
            ? g_kproj[(size_t)(b * N_ + idx) * (SH * DH) + s * DH + col]
            : Kb[s * DH + col];
    }
    __syncthreads();

#pragma unroll
    for (int ti = 0; ti < 4; ti++) {
        const int t  = wrp + ti * 8;
        const int nt = n0 + t * dil;
        const float4 ql = *reinterpret_cast<const float4*>(
            g_qproj + (size_t)(b * N_ + nt) * (SH * DH) + s * DH + lane * 4);
#pragma unroll
        for (int k = 0; k < KC; k++) {
            const float4 kf = *reinterpret_cast<const float4*>(&kv[t + k][lane * 4]);
            float p = ql.x*kf.x + ql.y*kf.y + ql.z*kf.z + ql.w*kf.w;
            p += __shfl_xor_sync(0xffffffffu, p, 16);
            p += __shfl_xor_sync(0xffffffffu, p, 8);
            p += __shfl_xor_sync(0xffffffffu, p, 4);
            p += __shfl_xor_sync(0xffffffffu, p, 2);
            p += __shfl_xor_sync(0xffffffffu, p, 1);
            if (lane == 0) ssc[t][k] = p;
        }
    }
    __syncthreads();

    const int hcnt = c_hcnt[s];
    for (int hi = 0; hi < hcnt; hi++) {
        const int h = c_hbase[s] + hi;

        for (int i = tid; i < KC * KC; i += 256)
            sks[i >> 5][i & 31] = Sk[(size_t)h * KC * KC + i];
        __syncthreads();

        for (int i = tid; i < 32 * KC; i += 256) {
            const int t = i & 31, j = i >> 5;
            float acc = Sb[h * KC + j];
#pragma unroll
            for (int k = 0; k < KC; k++) acc += ssc[t][k] * sks[j][k];
            shs[t][j] = acc;
        }
        __syncthreads();

        if (tid < 32) {
            float* row = shs[tid];
            float m = row[0];
#pragma unroll
            for (int j = 1; j < KC; j++) m = fmaxf(m, row[j]);
            float sum = 0.0f;
#pragma unroll
            for (int j = 0; j < KC; j++) { float e = expf(row[j]-m); row[j] = e; sum += e; }
            const float inv = 1.0f / sum;
#pragma unroll
            for (int j = 0; j < KC; j++) row[j] *= inv;
        }
        __syncthreads();

        for (int i = tid; i < 63 * DH; i += 256) {
            const int u = i >> 7, col = i & 127;
            const int idx = base + u * dil;
            kv[u][col] = (idx >= 0 && idx < N_)
                ? g_vproj[(size_t)(b * N_ + idx) * VW + h * DH + col]
                : Vb[h * DH + col];
        }
        __syncthreads();

        const int dq = lane * 4;
#pragma unroll
        for (int tt = 0; tt < 4; tt++) {
            const int t  = wrp + tt * 8;
            const int nt = n0 + t * dil;
            float4 acc = {0.f, 0.f, 0.f, 0.f};
#pragma unroll
            for (int j = 0; j < KC; j++) {
                const float wv = shs[t][j];
                const float4 v = *reinterpret_cast<const float4*>(&kv[t + j][dq]);
                acc.x += wv * v.x; acc.y += wv * v.y;
                acc.z += wv * v.z; acc.w += wv * v.w;
            }
            *reinterpret_cast<float4*>(
                g_attn + (size_t)(b * N_ + nt) * VW + h * DH + dq) = acc;
        }
        __syncthreads();
    }
}

extern "C" void kernel_launch(void* const* d_in, const int* in_sizes, int n_in,
                              void* d_out, int out_size)
{
    const float* query = (const float*)d_in[0];
    const float* key   = (const float*)d_in[1];
    const float* value = (const float*)d_in[2];
    const float* Qk    = (const float*)d_in[3];
    const float* Qb    = (const float*)d_in[4];
    const float* Kk    = (const float*)d_in[5];
    const float* Kb    = (const float*)d_in[6];
    const float* Vk    = (const float*)d_in[7];
    const float* Vb    = (const float*)d_in[8];
    const float* Sk    = (const float*)d_in[9];
    const float* Sb    = (const float*)d_in[10];
    const float* Ck    = (const float*)d_in[11];
    const float* Cb    = (const float*)d_in[12];
    float* out = (float*)d_out;

    __nv_bfloat16 *bq, *bk, *bv, *bQk, *bKk, *bVk, *bCk, *bat;
    float *ga;
    cudaGetSymbolAddress((void**)&bq,  gb_q);
    cudaGetSymbolAddress((void**)&bk,  gb_k);
    cudaGetSymbolAddress((void**)&bv,  gb_v);
    cudaGetSymbolAddress((void**)&bQk, gb_Qk);
    cudaGetSymbolAddress((void**)&bKk, gb_Kk);
    cudaGetSymbolAddress((void**)&bVk, gb_Vk);
    cudaGetSymbolAddress((void**)&bCk, gb_Ck);
    cudaGetSymbolAddress((void**)&bat, gb_at);
    cudaGetSymbolAddress((void**)&ga,  g_attn);

    const int M = B_ * N_;  // 2048

    // ---- operand expansion (fp32 -> bf16x3) ----
    auto cvt = [](const float* in, __nv_bfloat16* o, int R, int K, int mode) {
        const int pairs = R * K / 2;
        cvt_kernel<<<(pairs + 255) / 256, 256>>>(in, o, pairs, K, mode);
    };
    cvt(query, bq, M, DM, 0);
    cvt(key,   bk, M, DM, 0);
    cvt(value, bv, M, DM, 0);
    cvt(Qk, bQk, SH * DH, DM, 1);
    cvt(Kk, bKk, SH * DH, DM, 1);
    cvt(Vk, bVk, VW, DM, 1);
    cvt(Ck, bCk, DM, VW, 1);

    // ---- Q + K projections (tensor cores), grid (5,16,2) = 160 CTAs ----
    {
        dim3 grid(DM / 128, M / 128, 2);
        mma_qk_kernel<<<grid, 256>>>(Qb, Kb);
    }
    // ---- V projection, grid (14,16) = 224 CTAs ----
    {
        dim3 grid(VW / 128, M / 128);
        mma_v_kernel<<<grid, 256>>>(Vb);
    }
    // ---- fused banded attention (fp32) ----
    {
        dim3 grid(32, SH, B_);
        attn_fused_kernel<<<grid, 256>>>(Kb, Vb, Sk, Sb);
    }
    // ---- expand attn output, collapse GEMM split-K=2, bias add ----
    cvt(ga, bat, M, VW, 0);
    {
        dim3 grid(DM / 128, M / 128, 2);
        mma_col_kernel<<<grid, 256>>>();
    }
    add_bias_kernel<<<(M * DM / 4) / 256, 256>>>(Cb, out);
}

// round 6
// speedup vs baseline: 3.2252x; 1.1047x over previous
#include <cuda_runtime.h>
#include <cuda_bf16.h>
#include <cstdint>

#define B_    2
#define N_    1024
#define DM    640
#define SH    5
#define DH    128
#define NH    14
#define KC    32
#define VW    (NH * DH)       // 1792
#define QKVW  3072            // 640 + 640 + 1792 fused projection width
#define KOFF  640
#define VOFF  1280
#define KE_P  (3 * DM)        // 1920
#define KE_C  (3 * VW)        // 5376

// -------- fp32 device scratch --------
__device__ float g_qkv [B_ * N_ * QKVW];      // fused Q|K|V projections
__device__ float g_attn[B_ * N_ * NH * DH];
__device__ float g_part[2 * B_ * N_ * DM];

// -------- bf16x3-expanded operands --------
__device__ __nv_bfloat16 gb_q [B_ * N_ * KE_P];
__device__ __nv_bfloat16 gb_k [B_ * N_ * KE_P];
__device__ __nv_bfloat16 gb_v [B_ * N_ * KE_P];
__device__ __nv_bfloat16 gb_w [QKVW * KE_P];  // fused Qk|Kk|Vk weights
__device__ __nv_bfloat16 gb_Ck[DM * KE_C];
__device__ __nv_bfloat16 gb_at[B_ * N_ * KE_C];

__constant__ int c_dil  [SH] = {1, 1, 2, 4, 8};
__constant__ int c_hbase[SH] = {0, 5, 10, 12, 13};
__constant__ int c_hcnt [SH] = {5, 5, 2, 1, 1};

// ============================ helpers ======================================
__device__ __forceinline__ uint32_t smem_u32(const void* p) {
    return (uint32_t)__cvta_generic_to_shared(p);
}
__device__ __forceinline__ void cp_async16(uint32_t saddr, const void* g) {
    asm volatile("cp.async.cg.shared.global [%0], [%1], 16;"
                 :: "r"(saddr), "l"(g) : "memory");
}
#define CP_COMMIT() asm volatile("cp.async.commit_group;" ::: "memory")
#define CP_WAIT1()  asm volatile("cp.async.wait_group 1;"  ::: "memory")

__device__ __forceinline__ void ldmx4(uint32_t& r0, uint32_t& r1,
                                      uint32_t& r2, uint32_t& r3, uint32_t a) {
    asm volatile("ldmatrix.sync.aligned.m8n8.x4.shared.b16 {%0,%1,%2,%3}, [%4];"
        : "=r"(r0), "=r"(r1), "=r"(r2), "=r"(r3) : "r"(a));
}
__device__ __forceinline__ void mma16816(float* d, const uint32_t* a,
                                         const uint32_t b0, const uint32_t b1) {
    asm volatile(
        "mma.sync.aligned.m16n8k16.row.col.f32.bf16.bf16.f32 "
        "{%0,%1,%2,%3}, {%4,%5,%6,%7}, {%8,%9}, {%0,%1,%2,%3};"
        : "+f"(d[0]), "+f"(d[1]), "+f"(d[2]), "+f"(d[3])
        : "r"(a[0]), "r"(a[1]), "r"(a[2]), "r"(a[3]), "r"(b0), "r"(b1));
}

// ---------------------------------------------------------------------------
// HMMA bf16 GEMM with cp.async 3-stage pipeline.
// 128x128 tile, BK=32, 256 threads (8 warps 2x4), warp tile 64x32.
// Dynamic smem: 3 stages x (A 128x40 + B 128x40) bf16 = 61440 B.
// bias_tile: pre-offset to this CTA's 128-col tile (or nullptr).
// ---------------------------------------------------------------------------
#define BKT   32
#define LDS_  40            // 32 + 8 pad
#define ASZ   (128 * LDS_ * 2)
#define STAGE (2 * ASZ)     // A + B per stage
#define SMEM_GEMM (3 * STAGE)

__device__ __forceinline__ void hmma_gemm_body(
    const __nv_bfloat16* __restrict__ A, const __nv_bfloat16* __restrict__ W,
    const float* __restrict__ bias_tile, float* __restrict__ C,
    int Klen, int lda, int ldw, int ldc)
{
    extern __shared__ char smem[];
    const uint32_t smb = smem_u32(smem);

    const int bm = blockIdx.y * 128;
    const int bn = blockIdx.x * 128;
    const int tid = threadIdx.x;
    const int lane = tid & 31, wid = tid >> 5;
    const int wm = (wid & 1) * 64;
    const int wn = (wid >> 1) * 32;

    const int gr = tid >> 2;
    const int gc = (tid & 3) * 8;

    const __nv_bfloat16* Ap = A + (size_t)(bm + gr) * lda + gc;
    const __nv_bfloat16* Wp = W + (size_t)(bn + gr) * ldw + gc;

    const uint32_t sa0 = (uint32_t)(gr * LDS_ + gc) * 2;
    const uint32_t sa1 = (uint32_t)((gr + 64) * LDS_ + gc) * 2;

    float acc[4][4][4] = {};

    const int nk = Klen / BKT;
    auto issue = [&](int it2) {
        if (it2 < nk) {
            const int buf = it2 % 3;
            const uint32_t sA = smb + buf * STAGE;
            const uint32_t sB = sA + ASZ;
            const __nv_bfloat16* ap = Ap + it2 * BKT;
            const __nv_bfloat16* wp = Wp + it2 * BKT;
            cp_async16(sA + sa0, ap);
            cp_async16(sA + sa1, ap + (size_t)64 * lda);
            cp_async16(sB + sa0, wp);
            cp_async16(sB + sa1, wp + (size_t)64 * ldw);
        }
        CP_COMMIT();
    };

    issue(0);
    issue(1);

    // ldmatrix lane addressing (row 4 verified)
    const int a_row = wm + (lane & 15);
    const int a_kof = (lane >> 4) * 8;
    const int b_row = wn + (lane & 7) + (lane >> 4) * 8;
    const int b_kof = ((lane >> 3) & 1) * 8;

    for (int it = 0; it < nk; ++it) {
        CP_WAIT1();
        __syncthreads();
        issue(it + 2);

        const int buf = it % 3;
        const uint32_t sA = smb + buf * STAGE;
        const uint32_t sB = sA + ASZ;
#pragma unroll
        for (int ks = 0; ks < 2; ++ks) {
            const int k0 = ks * 16;
            uint32_t af[4][4], bf[2][4];
#pragma unroll
            for (int mi = 0; mi < 4; mi++)
                ldmx4(af[mi][0], af[mi][1], af[mi][2], af[mi][3],
                      sA + (uint32_t)((a_row + mi * 16) * LDS_ + k0 + a_kof) * 2);
#pragma unroll
            for (int g2 = 0; g2 < 2; g2++)
                ldmx4(bf[g2][0], bf[g2][1], bf[g2][2], bf[g2][3],
                      sB + (uint32_t)((b_row + g2 * 16) * LDS_ + k0 + b_kof) * 2);
#pragma unroll
            for (int mi = 0; mi < 4; mi++)
#pragma unroll
                for (int ni = 0; ni < 4; ni++)
                    mma16816(acc[mi][ni], af[mi],
                             bf[ni >> 1][(ni & 1) * 2], bf[ni >> 1][(ni & 1) * 2 + 1]);
        }
    }

    const int g = lane >> 2, t = lane & 3;
#pragma unroll
    for (int mi = 0; mi < 4; mi++) {
        const int row0 = bm + wm + mi * 16 + g;
#pragma unroll
        for (int ni = 0; ni < 4; ni++) {
            const int colL = wn + ni * 8 + t * 2;
            float b0 = 0.f, b1 = 0.f;
            if (bias_tile) { b0 = bias_tile[colL]; b1 = bias_tile[colL + 1]; }
            float2 v0 = {acc[mi][ni][0] + b0, acc[mi][ni][1] + b1};
            float2 v1 = {acc[mi][ni][2] + b0, acc[mi][ni][3] + b1};
            *reinterpret_cast<float2*>(&C[(size_t)row0 * ldc + bn + colL]) = v0;
            *reinterpret_cast<float2*>(&C[(size_t)(row0 + 8) * ldc + bn + colL]) = v1;
        }
    }
}

// Fused Q|K|V projection GEMM: grid (24, 16), output g_qkv (2048 x 3072).
__global__ __launch_bounds__(256) void hmma_qkv_kernel(
    const float* __restrict__ Qb, const float* __restrict__ Kb,
    const float* __restrict__ Vb)
{
    const int bn = blockIdx.x * 128;
    const __nv_bfloat16* A = (bn < KOFF) ? gb_q : (bn < VOFF) ? gb_k : gb_v;
    const float* bias = (bn < KOFF) ? (Qb + bn)
                      : (bn < VOFF) ? (Kb + bn - KOFF)
                                    : (Vb + bn - VOFF);
    hmma_gemm_body(A, gb_w, bias, g_qkv, KE_P, KE_P, KE_P, QKVW);
}

// Collapse GEMM split-K=2: grid (5, 16, 2).
__global__ __launch_bounds__(256) void hmma_col_kernel()
{
    const int z = blockIdx.z;
    const int koff = z * (KE_C / 2);
    hmma_gemm_body(gb_at + koff, gb_Ck + koff, nullptr,
                   g_part + (size_t)z * (B_ * N_ * DM), KE_C / 2, KE_C, KE_C, DM);
}

// ---------------------------------------------------------------------------
// fp32 -> bf16x3 expansion.  mode 0: [hi|hi|lo], mode 1: [hi|lo|hi]
// ---------------------------------------------------------------------------
__global__ __launch_bounds__(256) void cvt_kernel(
    const float* __restrict__ in, __nv_bfloat16* __restrict__ out,
    int total_pairs, int K, int mode)
{
    const int i = blockIdx.x * 256 + threadIdx.x;
    if (i >= total_pairs) return;
    const float2 x = reinterpret_cast<const float2*>(in)[i];
    const __nv_bfloat16 h0 = __float2bfloat16(x.x);
    const __nv_bfloat16 h1 = __float2bfloat16(x.y);
    const __nv_bfloat16 l0 = __float2bfloat16(x.x - __bfloat162float(h0));
    const __nv_bfloat16 l1 = __float2bfloat16(x.y - __bfloat162float(h1));
    __nv_bfloat162 hh; hh.x = h0; hh.y = h1;
    __nv_bfloat162 ll; ll.x = l0; ll.y = l1;
    const int k2 = K >> 1;
    const int r = i / k2, k = i % k2;
    __nv_bfloat162* orow = reinterpret_cast<__nv_bfloat162*>(out + (size_t)r * 3 * K);
    if (mode == 0) { orow[k] = hh; orow[k2 + k] = hh; orow[2 * k2 + k] = ll; }
    else           { orow[k] = hh; orow[k2 + k] = ll; orow[2 * k2 + k] = hh; }
}

__global__ __launch_bounds__(256) void add_bias_kernel(
    const float* __restrict__ Cb, float* __restrict__ out)
{
    const int i = blockIdx.x * 256 + threadIdx.x;
    const float4 p0 = reinterpret_cast<const float4*>(g_part)[i];
    const float4 p1 = reinterpret_cast<const float4*>(g_part + (size_t)B_ * N_ * DM)[i];
    const float4 bb = reinterpret_cast<const float4*>(Cb)[i % (DM / 4)];
    float4 o = {p0.x + p1.x + bb.x, p0.y + p1.y + bb.y,
                p0.z + p1.z + bb.z, p0.w + p1.w + bb.w};
    reinterpret_cast<float4*>(out)[i] = o;
}

// ---------------------------------------------------------------------------
// Fused banded attention (round-3 structure, reads fused g_qkv layout)
// ---------------------------------------------------------------------------
__global__ __launch_bounds__(256) void attn_fused_kernel(
    const float* __restrict__ Kb, const float* __restrict__ Vb,
    const float* __restrict__ Sk, const float* __restrict__ Sb)
{
    const int z   = blockIdx.x;
    const int s   = blockIdx.y;
    const int b   = blockIdx.z;
    const int tid = threadIdx.x;
    const int lane = tid & 31;
    const int wrp  = tid >> 5;

    const int dil = c_dil[s];
    const int pl  = ((KC - 1) * dil) >> 1;
    const int cpr = 32 / dil;
    const int r0  = z / cpr;
    const int c0  = z % cpr;
    const int n0  = r0 + c0 * 32 * dil;
    const int base = n0 - pl;

    __shared__ float kv [63][DH];
    __shared__ float ssc[32][33];
    __shared__ float sks[32][32];
    __shared__ float shs[32][33];

    for (int i = tid; i < 63 * DH; i += 256) {
        const int u = i >> 7, col = i & 127;
        const int idx = base + u * dil;
        kv[u][col] = (idx >= 0 && idx < N_)
            ? g_qkv[(size_t)(b * N_ + idx) * QKVW + KOFF + s * DH + col]
            : Kb[s * DH + col];
    }
    __syncthreads();

#pragma unroll
    for (int ti = 0; ti < 4; ti++) {
        const int t  = wrp + ti * 8;
        const int nt = n0 + t * dil;
        const float4 ql = *reinterpret_cast<const float4*>(
            g_qkv + (size_t)(b * N_ + nt) * QKVW + s * DH + lane * 4);
#pragma unroll
        for (int k = 0; k < KC; k++) {
            const float4 kf = *reinterpret_cast<const float4*>(&kv[t + k][lane * 4]);
            float p = ql.x*kf.x + ql.y*kf.y + ql.z*kf.z + ql.w*kf.w;
            p += __shfl_xor_sync(0xffffffffu, p, 16);
            p += __shfl_xor_sync(0xffffffffu, p, 8);
            p += __shfl_xor_sync(0xffffffffu, p, 4);
            p += __shfl_xor_sync(0xffffffffu, p, 2);
            p += __shfl_xor_sync(0xffffffffu, p, 1);
            if (lane == 0) ssc[t][k] = p;
        }
    }
    __syncthreads();

    const int hcnt = c_hcnt[s];
    for (int hi = 0; hi < hcnt; hi++) {
        const int h = c_hbase[s] + hi;

        for (int i = tid; i < KC * KC; i += 256)
            sks[i >> 5][i & 31] = Sk[(size_t)h * KC * KC + i];
        __syncthreads();

        for (int i = tid; i < 32 * KC; i += 256) {
            const int t = i & 31, j = i >> 5;
            float acc = Sb[h * KC + j];
#pragma unroll
            for (int k = 0; k < KC; k++) acc += ssc[t][k] * sks[j][k];
            shs[t][j] = acc;
        }
        __syncthreads();

        if (tid < 32) {
            float* rowp = shs[tid];
            float m = rowp[0];
#pragma unroll
            for (int j = 1; j < KC; j++) m = fmaxf(m, rowp[j]);
            float sum = 0.0f;
#pragma unroll
            for (int j = 0; j < KC; j++) { float e = expf(rowp[j]-m); rowp[j] = e; sum += e; }
            const float inv = 1.0f / sum;
#pragma unroll
            for (int j = 0; j < KC; j++) rowp[j] *= inv;
        }
        __syncthreads();

        for (int i = tid; i < 63 * DH; i += 256) {
            const int u = i >> 7, col = i & 127;
            const int idx = base + u * dil;
            kv[u][col] = (idx >= 0 && idx < N_)
                ? g_qkv[(size_t)(b * N_ + idx) * QKVW + VOFF + h * DH + col]
                : Vb[h * DH + col];
        }
        __syncthreads();

        const int dq = lane * 4;
#pragma unroll
        for (int tt = 0; tt < 4; tt++) {
            const int t  = wrp + tt * 8;
            const int nt = n0 + t * dil;
            float4 acc = {0.f, 0.f, 0.f, 0.f};
#pragma unroll
            for (int j = 0; j < KC; j++) {
                const float wv = shs[t][j];
                const float4 v = *reinterpret_cast<const float4*>(&kv[t + j][dq]);
                acc.x += wv * v.x; acc.y += wv * v.y;
                acc.z += wv * v.z; acc.w += wv * v.w;
            }
            *reinterpret_cast<float4*>(
                g_attn + (size_t)(b * N_ + nt) * VW + h * DH + dq) = acc;
        }
        __syncthreads();
    }
}

extern "C" void kernel_launch(void* const* d_in, const int* in_sizes, int n_in,
                              void* d_out, int out_size)
{
    const float* query = (const float*)d_in[0];
    const float* key   = (const float*)d_in[1];
    const float* value = (const float*)d_in[2];
    const float* Qk    = (const float*)d_in[3];
    const float* Qb    = (const float*)d_in[4];
    const float* Kk    = (const float*)d_in[5];
    const float* Kb    = (const float*)d_in[6];
    const float* Vk    = (const float*)d_in[7];
    const float* Vb    = (const float*)d_in[8];
    const float* Sk    = (const float*)d_in[9];
    const float* Sb    = (const float*)d_in[10];
    const float* Ck    = (const float*)d_in[11];
    const float* Cb    = (const float*)d_in[12];
    float* out = (float*)d_out;

    __nv_bfloat16 *bq, *bk, *bv, *bw, *bCk, *bat;
    float* ga;
    cudaGetSymbolAddress((void**)&bq,  gb_q);
    cudaGetSymbolAddress((void**)&bk,  gb_k);
    cudaGetSymbolAddress((void**)&bv,  gb_v);
    cudaGetSymbolAddress((void**)&bw,  gb_w);
    cudaGetSymbolAddress((void**)&bCk, gb_Ck);
    cudaGetSymbolAddress((void**)&bat, gb_at);
    cudaGetSymbolAddress((void**)&ga,  g_attn);

    cudaFuncSetAttribute(hmma_qkv_kernel,
        cudaFuncAttributeMaxDynamicSharedMemorySize, SMEM_GEMM);
    cudaFuncSetAttribute(hmma_col_kernel,
        cudaFuncAttributeMaxDynamicSharedMemorySize, SMEM_GEMM);

    const int M = B_ * N_;  // 2048

    auto cvt = [](const float* in, __nv_bfloat16* o, int R, int K, int mode) {
        const int pairs = R * K / 2;
        cvt_kernel<<<(pairs + 255) / 256, 256>>>(in, o, pairs, K, mode);
    };
    // activations
    cvt(query, bq, M, DM, 0);
    cvt(key,   bk, M, DM, 0);
    cvt(value, bv, M, DM, 0);
    // fused projection weights: rows [0,640)=Qk, [640,1280)=Kk, [1280,3072)=Vk
    cvt(Qk, bw,                          SH * DH, DM, 1);
    cvt(Kk, bw + (size_t)KOFF * KE_P,    SH * DH, DM, 1);
    cvt(Vk, bw + (size_t)VOFF * KE_P,    VW,      DM, 1);
    cvt(Ck, bCk, DM, VW, 1);

    {   // fused Q|K|V projection: grid (24, 16) = 384 CTAs
        dim3 grid(QKVW / 128, M / 128);
        hmma_qkv_kernel<<<grid, 256, SMEM_GEMM>>>(Qb, Kb, Vb);
    }
    {   // fused banded attention
        dim3 grid(32, SH, B_);
        attn_fused_kernel<<<grid, 256>>>(Kb, Vb, Sk, Sb);
    }
    cvt(ga, bat, M, VW, 0);
    {   // collapse split-K=2: grid (5, 16, 2) = 160 CTAs
        dim3 grid(DM / 128, M / 128, 2);
        hmma_col_kernel<<<grid, 256, SMEM_GEMM>>>();
    }
    add_bias_kernel<<<(M * DM / 4) / 256, 256>>>(Cb, out);
}

// round 7
// speedup vs baseline: 3.3083x; 1.0258x over previous
#include <cuda_runtime.h>
#include <cuda_bf16.h>
#include <cstdint>

#define B_    2
#define N_    1024
#define DM    640
#define SH    5
#define DH    128
#define NH    14
#define KC    32
#define VW    (NH * DH)       // 1792
#define QKVW  3072
#define KOFF  640
#define VOFF  1280
#define KE_P  (3 * DM)        // 1920
#define KE_C  (3 * VW)        // 5376

// -------- device scratch --------
__device__ float g_qkv [B_ * N_ * QKVW];
__device__ float g_part[2 * B_ * N_ * DM];

__device__ __nv_bfloat16 gb_q [B_ * N_ * KE_P];
__device__ __nv_bfloat16 gb_k [B_ * N_ * KE_P];
__device__ __nv_bfloat16 gb_v [B_ * N_ * KE_P];
__device__ __nv_bfloat16 gb_w [QKVW * KE_P];
__device__ __nv_bfloat16 gb_Ck[DM * KE_C];
__device__ __nv_bfloat16 gb_at[B_ * N_ * KE_C];   // attn out, bf16x3 [hi|hi|lo]

__constant__ int c_dil  [SH] = {1, 1, 2, 4, 8};
__constant__ int c_hbase[SH] = {0, 5, 10, 12, 13};
__constant__ int c_hcnt [SH] = {5, 5, 2, 1, 1};

// ============================ helpers ======================================
__device__ __forceinline__ uint32_t smem_u32(const void* p) {
    return (uint32_t)__cvta_generic_to_shared(p);
}
__device__ __forceinline__ void cp_async16(uint32_t saddr, const void* g) {
    asm volatile("cp.async.cg.shared.global [%0], [%1], 16;"
                 :: "r"(saddr), "l"(g) : "memory");
}
#define CP_COMMIT() asm volatile("cp.async.commit_group;" ::: "memory")
#define CP_WAIT1()  asm volatile("cp.async.wait_group 1;"  ::: "memory")

__device__ __forceinline__ void ldmx4(uint32_t& r0, uint32_t& r1,
                                      uint32_t& r2, uint32_t& r3, uint32_t a) {
    asm volatile("ldmatrix.sync.aligned.m8n8.x4.shared.b16 {%0,%1,%2,%3}, [%4];"
        : "=r"(r0), "=r"(r1), "=r"(r2), "=r"(r3) : "r"(a));
}
__device__ __forceinline__ void mma16816(float* d, const uint32_t* a,
                                         const uint32_t b0, const uint32_t b1) {
    asm volatile(
        "mma.sync.aligned.m16n8k16.row.col.f32.bf16.bf16.f32 "
        "{%0,%1,%2,%3}, {%4,%5,%6,%7}, {%8,%9}, {%0,%1,%2,%3};"
        : "+f"(d[0]), "+f"(d[1]), "+f"(d[2]), "+f"(d[3])
        : "r"(a[0]), "r"(a[1]), "r"(a[2]), "r"(a[3]), "r"(b0), "r"(b1));
}

// ---------------------------------------------------------------------------
// HMMA bf16 GEMM, cp.async 3-stage, BK=64, 128x128 tile, 256 threads.
// ---------------------------------------------------------------------------
#define BKT   64
#define LDS_  72                // 64 + 8 pad (bf16 elems)
#define ASZ   (128 * LDS_ * 2)  // 18432 B
#define STAGE (2 * ASZ)         // 36864 B
#define SMEM_GEMM (3 * STAGE)   // 110592 B

__device__ __forceinline__ void hmma_gemm_body(
    const __nv_bfloat16* __restrict__ A, const __nv_bfloat16* __restrict__ W,
    const float* __restrict__ bias_tile, float* __restrict__ C,
    int Klen, int lda, int ldw, int ldc)
{
    extern __shared__ char smem[];
    const uint32_t smb = smem_u32(smem);

    const int bm = blockIdx.y * 128;
    const int bn = blockIdx.x * 128;
    const int tid = threadIdx.x;
    const int lane = tid & 31, wid = tid >> 5;
    const int wm = (wid & 1) * 64;
    const int wn = (wid >> 1) * 32;

    const int gr = tid >> 2;            // 0..63
    const int gc = (tid & 3) * 8;       // 0,8,16,24

    const __nv_bfloat16* Ap = A + (size_t)(bm + gr) * lda + gc;
    const __nv_bfloat16* Wp = W + (size_t)(bn + gr) * ldw + gc;

    const uint32_t s00 = (uint32_t)(gr * LDS_ + gc) * 2;
    const uint32_t s01 = s00 + 64;                       // +32 cols
    const uint32_t s10 = (uint32_t)((gr + 64) * LDS_ + gc) * 2;
    const uint32_t s11 = s10 + 64;

    float acc[4][4][4] = {};

    const int nk = Klen / BKT;
    auto issue = [&](int it2) {
        if (it2 < nk) {
            const int buf = it2 % 3;
            const uint32_t sA = smb + buf * STAGE;
            const uint32_t sB = sA + ASZ;
            const __nv_bfloat16* ap = Ap + it2 * BKT;
            const __nv_bfloat16* wp = Wp + it2 * BKT;
            cp_async16(sA + s00, ap);
            cp_async16(sA + s01, ap + 32);
            cp_async16(sA + s10, ap + (size_t)64 * lda);
            cp_async16(sA + s11, ap + (size_t)64 * lda + 32);
            cp_async16(sB + s00, wp);
            cp_async16(sB + s01, wp + 32);
            cp_async16(sB + s10, wp + (size_t)64 * ldw);
            cp_async16(sB + s11, wp + (size_t)64 * ldw + 32);
        }
        CP_COMMIT();
    };

    issue(0);
    issue(1);

    const int a_row = wm + (lane & 15);
    const int a_kof = (lane >> 4) * 8;
    const int b_row = wn + (lane & 7) + (lane >> 4) * 8;
    const int b_kof = ((lane >> 3) & 1) * 8;

    for (int it = 0; it < nk; ++it) {
        CP_WAIT1();
        __syncthreads();
        issue(it + 2);

        const int buf = it % 3;
        const uint32_t sA = smb + buf * STAGE;
        const uint32_t sB = sA + ASZ;
#pragma unroll
        for (int ks = 0; ks < 4; ++ks) {
            const int k0 = ks * 16;
            uint32_t af[4][4], bf[2][4];
#pragma unroll
            for (int mi = 0; mi < 4; mi++)
                ldmx4(af[mi][0], af[mi][1], af[mi][2], af[mi][3],
                      sA + (uint32_t)((a_row + mi * 16) * LDS_ + k0 + a_kof) * 2);
#pragma unroll
            for (int g2 = 0; g2 < 2; g2++)
                ldmx4(bf[g2][0], bf[g2][1], bf[g2][2], bf[g2][3],
                      sB + (uint32_t)((b_row + g2 * 16) * LDS_ + k0 + b_kof) * 2);
#pragma unroll
            for (int mi = 0; mi < 4; mi++)
#pragma unroll
                for (int ni = 0; ni < 4; ni++)
                    mma16816(acc[mi][ni], af[mi],
                             bf[ni >> 1][(ni & 1) * 2], bf[ni >> 1][(ni & 1) * 2 + 1]);
        }
    }

    const int g = lane >> 2, t = lane & 3;
#pragma unroll
    for (int mi = 0; mi < 4; mi++) {
        const int row0 = bm + wm + mi * 16 + g;
#pragma unroll
        for (int ni = 0; ni < 4; ni++) {
            const int colL = wn + ni * 8 + t * 2;
            float b0 = 0.f, b1 = 0.f;
            if (bias_tile) { b0 = bias_tile[colL]; b1 = bias_tile[colL + 1]; }
            float2 v0 = {acc[mi][ni][0] + b0, acc[mi][ni][1] + b1};
            float2 v1 = {acc[mi][ni][2] + b0, acc[mi][ni][3] + b1};
            *reinterpret_cast<float2*>(&C[(size_t)row0 * ldc + bn + colL]) = v0;
            *reinterpret_cast<float2*>(&C[(size_t)(row0 + 8) * ldc + bn + colL]) = v1;
        }
    }
}

__global__ __launch_bounds__(256) void hmma_qkv_kernel(
    const float* __restrict__ Qb, const float* __restrict__ Kb,
    const float* __restrict__ Vb)
{
    const int bn = blockIdx.x * 128;
    const __nv_bfloat16* A = (bn < KOFF) ? gb_q : (bn < VOFF) ? gb_k : gb_v;
    const float* bias = (bn < KOFF) ? (Qb + bn)
                      : (bn < VOFF) ? (Kb + bn - KOFF)
                                    : (Vb + bn - VOFF);
    hmma_gemm_body(A, gb_w, bias, g_qkv, KE_P, KE_P, KE_P, QKVW);
}

__global__ __launch_bounds__(256) void hmma_col_kernel()
{
    const int z = blockIdx.z;
    const int koff = z * (KE_C / 2);
    hmma_gemm_body(gb_at + koff, gb_Ck + koff, nullptr,
                   g_part + (size_t)z * (B_ * N_ * DM), KE_C / 2, KE_C, KE_C, DM);
}

// ---------------------------------------------------------------------------
// fp32 -> bf16x3.  mode 0: [hi|hi|lo], mode 1: [hi|lo|hi]
// ---------------------------------------------------------------------------
__device__ __forceinline__ void cvt_body(
    const float* __restrict__ in, __nv_bfloat16* __restrict__ out,
    int i, int K, int mode)
{
    const float2 x = reinterpret_cast<const float2*>(in)[i];
    const __nv_bfloat16 h0 = __float2bfloat16(x.x);
    const __nv_bfloat16 h1 = __float2bfloat16(x.y);
    const __nv_bfloat16 l0 = __float2bfloat16(x.x - __bfloat162float(h0));
    const __nv_bfloat16 l1 = __float2bfloat16(x.y - __bfloat162float(h1));
    __nv_bfloat162 hh; hh.x = h0; hh.y = h1;
    __nv_bfloat162 ll; ll.x = l0; ll.y = l1;
    const int k2 = K >> 1;
    const int r = i / k2, k = i % k2;
    __nv_bfloat162* orow = reinterpret_cast<__nv_bfloat162*>(out + (size_t)r * 3 * K);
    if (mode == 0) { orow[k] = hh; orow[k2 + k] = hh; orow[2 * k2 + k] = ll; }
    else           { orow[k] = hh; orow[k2 + k] = ll; orow[2 * k2 + k] = hh; }
}

__global__ __launch_bounds__(256) void cvt_kernel(
    const float* __restrict__ in, __nv_bfloat16* __restrict__ out,
    int total_pairs, int K, int mode)
{
    const int i = blockIdx.x * 256 + threadIdx.x;
    if (i < total_pairs) cvt_body(in, out, i, K, mode);
}

// batched q/k/v activation conversion (blockIdx.y selects tensor)
__global__ __launch_bounds__(256) void cvt_qkv_kernel(
    const float* __restrict__ q, const float* __restrict__ k,
    const float* __restrict__ v)
{
    const int i = blockIdx.x * 256 + threadIdx.x;
    if (i >= B_ * N_ * DM / 2) return;
    const int which = blockIdx.y;
    const float* in = (which == 0) ? q : (which == 1) ? k : v;
    __nv_bfloat16* out = (which == 0) ? gb_q : (which == 1) ? gb_k : gb_v;
    cvt_body(in, out, i, DM, 0);
}

__global__ __launch_bounds__(256) void add_bias_kernel(
    const float* __restrict__ Cb, float* __restrict__ out)
{
    const int i = blockIdx.x * 256 + threadIdx.x;
    const float4 p0 = reinterpret_cast<const float4*>(g_part)[i];
    const float4 p1 = reinterpret_cast<const float4*>(g_part + (size_t)B_ * N_ * DM)[i];
    const float4 bb = reinterpret_cast<const float4*>(Cb)[i % (DM / 4)];
    float4 o = {p0.x + p1.x + bb.x, p0.y + p1.y + bb.y,
                p0.z + p1.z + bb.z, p0.w + p1.w + bb.w};
    reinterpret_cast<float4*>(out)[i] = o;
}

// ---------------------------------------------------------------------------
// Fused banded attention; epilogue writes bf16x3 [hi|hi|lo] directly to gb_at.
// ---------------------------------------------------------------------------
__global__ __launch_bounds__(256) void attn_fused_kernel(
    const float* __restrict__ Kb, const float* __restrict__ Vb,
    const float* __restrict__ Sk, const float* __restrict__ Sb)
{
    const int z   = blockIdx.x;
    const int s   = blockIdx.y;
    const int b   = blockIdx.z;
    const int tid = threadIdx.x;
    const int lane = tid & 31;
    const int wrp  = tid >> 5;

    const int dil = c_dil[s];
    const int pl  = ((KC - 1) * dil) >> 1;
    const int cpr = 32 / dil;
    const int r0  = z / cpr;
    const int c0  = z % cpr;
    const int n0  = r0 + c0 * 32 * dil;
    const int base = n0 - pl;

    __shared__ float kv [63][DH];
    __shared__ float ssc[32][33];
    __shared__ float sks[32][32];
    __shared__ float shs[32][33];

    for (int i = tid; i < 63 * DH; i += 256) {
        const int u = i >> 7, col = i & 127;
        const int idx = base + u * dil;
        kv[u][col] = (idx >= 0 && idx < N_)
            ? g_qkv[(size_t)(b * N_ + idx) * QKVW + KOFF + s * DH + col]
            : Kb[s * DH + col];
    }
    __syncthreads();

#pragma unroll
    for (int ti = 0; ti < 4; ti++) {
        const int t  = wrp + ti * 8;
        const int nt = n0 + t * dil;
        const float4 ql = *reinterpret_cast<const float4*>(
            g_qkv + (size_t)(b * N_ + nt) * QKVW + s * DH + lane * 4);
#pragma unroll
        for (int k = 0; k < KC; k++) {
            const float4 kf = *reinterpret_cast<const float4*>(&kv[t + k][lane * 4]);
            float p = ql.x*kf.x + ql.y*kf.y + ql.z*kf.z + ql.w*kf.w;
            p += __shfl_xor_sync(0xffffffffu, p, 16);
            p += __shfl_xor_sync(0xffffffffu, p, 8);
            p += __shfl_xor_sync(0xffffffffu, p, 4);
            p += __shfl_xor_sync(0xffffffffu, p, 2);
            p += __shfl_xor_sync(0xffffffffu, p, 1);
            if (lane == 0) ssc[t][k] = p;
        }
    }
    __syncthreads();

    const int hcnt = c_hcnt[s];
    for (int hi = 0; hi < hcnt; hi++) {
        const int h = c_hbase[s] + hi;

        for (int i = tid; i < KC * KC; i += 256)
            sks[i >> 5][i & 31] = Sk[(size_t)h * KC * KC + i];
        __syncthreads();

        for (int i = tid; i < 32 * KC; i += 256) {
            const int t = i & 31, j = i >> 5;
            float acc = Sb[h * KC + j];
#pragma unroll
            for (int k = 0; k < KC; k++) acc += ssc[t][k] * sks[j][k];
            shs[t][j] = acc;
        }
        __syncthreads();

        if (tid < 32) {
            float* rowp = shs[tid];
            float m = rowp[0];
#pragma unroll
            for (int j = 1; j < KC; j++) m = fmaxf(m, rowp[j]);
            float sum = 0.0f;
#pragma unroll
            for (int j = 0; j < KC; j++) { float e = expf(rowp[j]-m); rowp[j] = e; sum += e; }
            const float inv = 1.0f / sum;
#pragma unroll
            for (int j = 0; j < KC; j++) rowp[j] *= inv;
        }
        __syncthreads();

        for (int i = tid; i < 63 * DH; i += 256) {
            const int u = i >> 7, col = i & 127;
            const int idx = base + u * dil;
            kv[u][col] = (idx >= 0 && idx < N_)
                ? g_qkv[(size_t)(b * N_ + idx) * QKVW + VOFF + h * DH + col]
                : Vb[h * DH + col];
        }
        __syncthreads();

        const int dq = lane * 4;
#pragma unroll
        for (int tt = 0; tt < 4; tt++) {
            const int t  = wrp + tt * 8;
            const int nt = n0 + t * dil;
            float4 acc = {0.f, 0.f, 0.f, 0.f};
#pragma unroll
            for (int j = 0; j < KC; j++) {
                const float wv = shs[t][j];
                const float4 v = *reinterpret_cast<const float4*>(&kv[t + j][dq]);
                acc.x += wv * v.x; acc.y += wv * v.y;
                acc.z += wv * v.z; acc.w += wv * v.w;
            }
            // write bf16x3 [hi|hi|lo] directly (activation layout for collapse)
            __nv_bfloat16 h0 = __float2bfloat16(acc.x);
            __nv_bfloat16 h1 = __float2bfloat16(acc.y);
            __nv_bfloat16 h2 = __float2bfloat16(acc.z);
            __nv_bfloat16 h3 = __float2bfloat16(acc.w);
            __nv_bfloat16 l0 = __float2bfloat16(acc.x - __bfloat162float(h0));
            __nv_bfloat16 l1 = __float2bfloat16(acc.y - __bfloat162float(h1));
            __nv_bfloat16 l2 = __float2bfloat16(acc.z - __bfloat162float(h2));
            __nv_bfloat16 l3 = __float2bfloat16(acc.w - __bfloat162float(h3));
            uint2 hv, lv;
            __nv_bfloat162 hp0; hp0.x = h0; hp0.y = h1;
            __nv_bfloat162 hp1; hp1.x = h2; hp1.y = h3;
            __nv_bfloat162 lp0; lp0.x = l0; lp0.y = l1;
            __nv_bfloat162 lp1; lp1.x = l2; lp1.y = l3;
            hv.x = *reinterpret_cast<uint32_t*>(&hp0);
            hv.y = *reinterpret_cast<uint32_t*>(&hp1);
            lv.x = *reinterpret_cast<uint32_t*>(&lp0);
            lv.y = *reinterpret_cast<uint32_t*>(&lp1);
            __nv_bfloat16* orow = gb_at + (size_t)(b * N_ + nt) * KE_C;
            const int col = h * DH + dq;
            *reinterpret_cast<uint2*>(orow + col)            = hv;
            *reinterpret_cast<uint2*>(orow + VW + col)       = hv;
            *reinterpret_cast<uint2*>(orow + 2 * VW + col)   = lv;
        }
        __syncthreads();
    }
}

extern "C" void kernel_launch(void* const* d_in, const int* in_sizes, int n_in,
                              void* d_out, int out_size)
{
    const float* query = (const float*)d_in[0];
    const float* key   = (const float*)d_in[1];
    const float* value = (const float*)d_in[2];
    const float* Qk    = (const float*)d_in[3];
    const float* Qb    = (const float*)d_in[4];
    const float* Kk    = (const float*)d_in[5];
    const float* Kb    = (const float*)d_in[6];
    const float* Vk    = (const float*)d_in[7];
    const float* Vb    = (const float*)d_in[8];
    const float* Sk    = (const float*)d_in[9];
    const float* Sb    = (const float*)d_in[10];
    const float* Ck    = (const float*)d_in[11];
    const float* Cb    = (const float*)d_in[12];
    float* out = (float*)d_out;

    __nv_bfloat16 *bw, *bCk;
    cudaGetSymbolAddress((void**)&bw,  gb_w);
    cudaGetSymbolAddress((void**)&bCk, gb_Ck);

    cudaFuncSetAttribute(hmma_qkv_kernel,
        cudaFuncAttributeMaxDynamicSharedMemorySize, SMEM_GEMM);
    cudaFuncSetAttribute(hmma_col_kernel,
        cudaFuncAttributeMaxDynamicSharedMemorySize, SMEM_GEMM);

    const int M = B_ * N_;  // 2048

    // activations q/k/v in one launch
    {
        const int pairs = M * DM / 2;
        dim3 grid((pairs + 255) / 256, 3);
        cvt_qkv_kernel<<<grid, 256>>>(query, key, value);
    }
    auto cvt = [](const float* in, __nv_bfloat16* o, int R, int K, int mode) {
        const int pairs = R * K / 2;
        cvt_kernel<<<(pairs + 255) / 256, 256>>>(in, o, pairs, K, mode);
    };
    cvt(Qk, bw,                       SH * DH, DM, 1);
    cvt(Kk, bw + (size_t)KOFF * KE_P, SH * DH, DM, 1);
    cvt(Vk, bw + (size_t)VOFF * KE_P, VW,      DM, 1);
    cvt(Ck, bCk, DM, VW, 1);

    {   // fused Q|K|V projection: grid (24, 16)
        dim3 grid(QKVW / 128, M / 128);
        hmma_qkv_kernel<<<grid, 256, SMEM_GEMM>>>(Qb, Kb, Vb);
    }
    {   // fused banded attention (writes gb_at bf16x3 directly)
        dim3 grid(32, SH, B_);
        attn_fused_kernel<<<grid, 256>>>(Kb, Vb, Sk, Sb);
    }
    {   // collapse split-K=2: grid (5, 16, 2)
        dim3 grid(DM / 128, M / 128, 2);
        hmma_col_kernel<<<grid, 256, SMEM_GEMM>>>();
    }
    add_bias_kernel<<<(M * DM / 4) / 256, 256>>>(Cb, out);
}

// round 8
// speedup vs baseline: 4.0349x; 1.2196x over previous
#include <cuda_runtime.h>
#include <cuda_bf16.h>
#include <cstdint>

#define B_    2
#define N_    1024
#define DM    640
#define SH    5
#define DH    128
#define NH    14
#define KC    32
#define VW    (NH * DH)       // 1792
#define QKVW  3072
#define KOFF  640
#define VOFF  1280
#define KE_P  (3 * DM)        // 1920
#define KE_C  (3 * VW)        // 5376
#define ZSPLIT 3              // collapse split-K ways (5376/3 = 1792, /64 = 28)

// -------- device scratch --------
__device__ float g_qkv [B_ * N_ * QKVW];
__device__ float g_part[ZSPLIT * B_ * N_ * DM];

__device__ __nv_bfloat16 gb_q [B_ * N_ * KE_P];
__device__ __nv_bfloat16 gb_k [B_ * N_ * KE_P];
__device__ __nv_bfloat16 gb_v [B_ * N_ * KE_P];
__device__ __nv_bfloat16 gb_w [QKVW * KE_P];
__device__ __nv_bfloat16 gb_Ck[DM * KE_C];
__device__ __nv_bfloat16 gb_at[B_ * N_ * KE_C];   // attn out, bf16x3 [hi|hi|lo]

__constant__ int c_dil  [SH] = {1, 1, 2, 4, 8};
__constant__ int c_hbase[SH] = {0, 5, 10, 12, 13};
__constant__ int c_hcnt [SH] = {5, 5, 2, 1, 1};

// ============================ helpers ======================================
__device__ __forceinline__ uint32_t smem_u32(const void* p) {
    return (uint32_t)__cvta_generic_to_shared(p);
}
__device__ __forceinline__ void cp_async16(uint32_t saddr, const void* g) {
    asm volatile("cp.async.cg.shared.global [%0], [%1], 16;"
                 :: "r"(saddr), "l"(g) : "memory");
}
#define CP_COMMIT() asm volatile("cp.async.commit_group;" ::: "memory")
#define CP_WAIT1()  asm volatile("cp.async.wait_group 1;"  ::: "memory")

__device__ __forceinline__ void ldmx4(uint32_t& r0, uint32_t& r1,
                                      uint32_t& r2, uint32_t& r3, uint32_t a) {
    asm volatile("ldmatrix.sync.aligned.m8n8.x4.shared.b16 {%0,%1,%2,%3}, [%4];"
        : "=r"(r0), "=r"(r1), "=r"(r2), "=r"(r3) : "r"(a));
}
__device__ __forceinline__ void mma16816(float* d, const uint32_t* a,
                                         const uint32_t b0, const uint32_t b1) {
    asm volatile(
        "mma.sync.aligned.m16n8k16.row.col.f32.bf16.bf16.f32 "
        "{%0,%1,%2,%3}, {%4,%5,%6,%7}, {%8,%9}, {%0,%1,%2,%3};"
        : "+f"(d[0]), "+f"(d[1]), "+f"(d[2]), "+f"(d[3])
        : "r"(a[0]), "r"(a[1]), "r"(a[2]), "r"(a[3]), "r"(b0), "r"(b1));
}

// ---------------------------------------------------------------------------
// HMMA bf16 GEMM, cp.async 3-stage, BK=64, 128x128 CTA tile, 128 threads
// (4 warps, 64x64 warp tile). 2 CTAs/SM (smem 110.6 KB, regs ~190/thr).
// ---------------------------------------------------------------------------
#define BKT   64
#define LDS_  72                // 64 + 8 pad (bf16 elems)
#define ASZ   (128 * LDS_ * 2)  // 18432 B
#define STAGE (2 * ASZ)         // 36864 B
#define SMEM_GEMM (3 * STAGE)   // 110592 B

__device__ __forceinline__ void hmma_gemm_body(
    const __nv_bfloat16* __restrict__ A, const __nv_bfloat16* __restrict__ W,
    const float* __restrict__ bias_tile, float* __restrict__ C,
    int Klen, int lda, int ldw, int ldc)
{
    extern __shared__ char smem[];
    const uint32_t smb = smem_u32(smem);

    const int bm = blockIdx.y * 128;
    const int bn = blockIdx.x * 128;
    const int tid = threadIdx.x;           // 0..127
    const int lane = tid & 31, wid = tid >> 5;   // 4 warps
    const int wm = (wid & 1) * 64;
    const int wn = (wid >> 1) * 64;

    float acc[4][8][4] = {};

    const int nk = Klen / BKT;
    // load mapping: 8 chunks each for A and B; idx = tid + i*128,
    // row = idx>>3 (0..127), col chunk = (idx&7)*8 (0..56)
    auto issue = [&](int it2) {
        if (it2 < nk) {
            const int buf = it2 % 3;
            const uint32_t sA = smb + buf * STAGE;
            const uint32_t sB = sA + ASZ;
            const __nv_bfloat16* abase = A + it2 * BKT;
            const __nv_bfloat16* wbase = W + it2 * BKT;
#pragma unroll
            for (int i = 0; i < 8; i++) {
                const int idx = tid + i * 128;
                const int row = idx >> 3;
                const int col = (idx & 7) * 8;
                const uint32_t so = (uint32_t)(row * LDS_ + col) * 2;
                cp_async16(sA + so, abase + (size_t)(bm + row) * lda + col);
                cp_async16(sB + so, wbase + (size_t)(bn + row) * ldw + col);
            }
        }
        CP_COMMIT();
    };

    issue(0);
    issue(1);

    const int a_row = wm + (lane & 15);
    const int a_kof = (lane >> 4) * 8;
    const int b_row = wn + (lane & 7) + (lane >> 4) * 8;
    const int b_kof = ((lane >> 3) & 1) * 8;

    for (int it = 0; it < nk; ++it) {
        CP_WAIT1();
        __syncthreads();
        issue(it + 2);

        const int buf = it % 3;
        const uint32_t sA = smb + buf * STAGE;
        const uint32_t sB = sA + ASZ;
#pragma unroll
        for (int ks = 0; ks < 4; ++ks) {
            const int k0 = ks * 16;
            uint32_t af[4][4], bf[4][4];
#pragma unroll
            for (int mi = 0; mi < 4; mi++)
                ldmx4(af[mi][0], af[mi][1], af[mi][2], af[mi][3],
                      sA + (uint32_t)((a_row + mi * 16) * LDS_ + k0 + a_kof) * 2);
#pragma unroll
            for (int g2 = 0; g2 < 4; g2++)
                ldmx4(bf[g2][0], bf[g2][1], bf[g2][2], bf[g2][3],
                      sB + (uint32_t)((b_row + g2 * 16) * LDS_ + k0 + b_kof) * 2);
#pragma unroll
            for (int mi = 0; mi < 4; mi++)
#pragma unroll
                for (int ni = 0; ni < 8; ni++)
                    mma16816(acc[mi][ni], af[mi],
                             bf[ni >> 1][(ni & 1) * 2], bf[ni >> 1][(ni & 1) * 2 + 1]);
        }
    }

    const int g = lane >> 2, t = lane & 3;
#pragma unroll
    for (int mi = 0; mi < 4; mi++) {
        const int row0 = bm + wm + mi * 16 + g;
#pragma unroll
        for (int ni = 0; ni < 8; ni++) {
            const int colL = wn + ni * 8 + t * 2;
            float b0 = 0.f, b1 = 0.f;
            if (bias_tile) { b0 = bias_tile[colL]; b1 = bias_tile[colL + 1]; }
            float2 v0 = {acc[mi][ni][0] + b0, acc[mi][ni][1] + b1};
            float2 v1 = {acc[mi][ni][2] + b0, acc[mi][ni][3] + b1};
            *reinterpret_cast<float2*>(&C[(size_t)row0 * ldc + bn + colL]) = v0;
            *reinterpret_cast<float2*>(&C[(size_t)(row0 + 8) * ldc + bn + colL]) = v1;
        }
    }
}

__global__ __launch_bounds__(128) void hmma_qkv_kernel(
    const float* __restrict__ Qb, const float* __restrict__ Kb,
    const float* __restrict__ Vb)
{
    const int bn = blockIdx.x * 128;
    const __nv_bfloat16* A = (bn < KOFF) ? gb_q : (bn < VOFF) ? gb_k : gb_v;
    const float* bias = (bn < KOFF) ? (Qb + bn)
                      : (bn < VOFF) ? (Kb + bn - KOFF)
                                    : (Vb + bn - VOFF);
    hmma_gemm_body(A, gb_w, bias, g_qkv, KE_P, KE_P, KE_P, QKVW);
}

__global__ __launch_bounds__(128) void hmma_col_kernel()
{
    const int z = blockIdx.z;
    const int koff = z * (KE_C / ZSPLIT);
    hmma_gemm_body(gb_at + koff, gb_Ck + koff, nullptr,
                   g_part + (size_t)z * (B_ * N_ * DM),
                   KE_C / ZSPLIT, KE_C, KE_C, DM);
}

// ---------------------------------------------------------------------------
// fp32 -> bf16x3.  mode 0: [hi|hi|lo], mode 1: [hi|lo|hi]
// ---------------------------------------------------------------------------
__device__ __forceinline__ void cvt_body(
    const float* __restrict__ in, __nv_bfloat16* __restrict__ out,
    int i, int K, int mode)
{
    const float2 x = reinterpret_cast<const float2*>(in)[i];
    const __nv_bfloat16 h0 = __float2bfloat16(x.x);
    const __nv_bfloat16 h1 = __float2bfloat16(x.y);
    const __nv_bfloat16 l0 = __float2bfloat16(x.x - __bfloat162float(h0));
    const __nv_bfloat16 l1 = __float2bfloat16(x.y - __bfloat162float(h1));
    __nv_bfloat162 hh; hh.x = h0; hh.y = h1;
    __nv_bfloat162 ll; ll.x = l0; ll.y = l1;
    const int k2 = K >> 1;
    const int r = i / k2, k = i % k2;
    __nv_bfloat162* orow = reinterpret_cast<__nv_bfloat162*>(out + (size_t)r * 3 * K);
    if (mode == 0) { orow[k] = hh; orow[k2 + k] = hh; orow[2 * k2 + k] = ll; }
    else           { orow[k] = hh; orow[k2 + k] = ll; orow[2 * k2 + k] = hh; }
}

__global__ __launch_bounds__(256) void cvt_kernel(
    const float* __restrict__ in, __nv_bfloat16* __restrict__ out,
    int total_pairs, int K, int mode)
{
    const int i = blockIdx.x * 256 + threadIdx.x;
    if (i < total_pairs) cvt_body(in, out, i, K, mode);
}

__global__ __launch_bounds__(256) void cvt_qkv_kernel(
    const float* __restrict__ q, const float* __restrict__ k,
    const float* __restrict__ v)
{
    const int i = blockIdx.x * 256 + threadIdx.x;
    if (i >= B_ * N_ * DM / 2) return;
    const int which = blockIdx.y;
    const float* in = (which == 0) ? q : (which == 1) ? k : v;
    __nv_bfloat16* out = (which == 0) ? gb_q : (which == 1) ? gb_k : gb_v;
    cvt_body(in, out, i, DM, 0);
}

__global__ __launch_bounds__(256) void add_bias_kernel(
    const float* __restrict__ Cb, float* __restrict__ out)
{
    const int i = blockIdx.x * 256 + threadIdx.x;
    const float4 p0 = reinterpret_cast<const float4*>(g_part)[i];
    const float4 p1 = reinterpret_cast<const float4*>(g_part + (size_t)B_ * N_ * DM)[i];
    const float4 p2 = reinterpret_cast<const float4*>(g_part + (size_t)2 * B_ * N_ * DM)[i];
    const float4 bb = reinterpret_cast<const float4*>(Cb)[i % (DM / 4)];
    float4 o = {p0.x + p1.x + p2.x + bb.x, p0.y + p1.y + p2.y + bb.y,
                p0.z + p1.z + p2.z + bb.z, p0.w + p1.w + p2.w + bb.w};
    reinterpret_cast<float4*>(out)[i] = o;
}

// ---------------------------------------------------------------------------
// Fused banded attention; epilogue writes bf16x3 [hi|hi|lo] directly to gb_at.
// ---------------------------------------------------------------------------
__global__ __launch_bounds__(256) void attn_fused_kernel(
    const float* __restrict__ Kb, const float* __restrict__ Vb,
    const float* __restrict__ Sk, const float* __restrict__ Sb)
{
    const int z   = blockIdx.x;
    const int s   = blockIdx.y;
    const int b   = blockIdx.z;
    const int tid = threadIdx.x;
    const int lane = tid & 31;
    const int wrp  = tid >> 5;

    const int dil = c_dil[s];
    const int pl  = ((KC - 1) * dil) >> 1;
    const int cpr = 32 / dil;
    const int r0  = z / cpr;
    const int c0  = z % cpr;
    const int n0  = r0 + c0 * 32 * dil;
    const int base = n0 - pl;

    __shared__ float kv [63][DH];
    __shared__ float ssc[32][33];
    __shared__ float sks[32][32];
    __shared__ float shs[32][33];

    for (int i = tid; i < 63 * DH; i += 256) {
        const int u = i >> 7, col = i & 127;
        const int idx = base + u * dil;
        kv[u][col] = (idx >= 0 && idx < N_)
            ? g_qkv[(size_t)(b * N_ + idx) * QKVW + KOFF + s * DH + col]
            : Kb[s * DH + col];
    }
    __syncthreads();

#pragma unroll
    for (int ti = 0; ti < 4; ti++) {
        const int t  = wrp + ti * 8;
        const int nt = n0 + t * dil;
        const float4 ql = *reinterpret_cast<const float4*>(
            g_qkv + (size_t)(b * N_ + nt) * QKVW + s * DH + lane * 4);
#pragma unroll
        for (int k = 0; k < KC; k++) {
            const float4 kf = *reinterpret_cast<const float4*>(&kv[t + k][lane * 4]);
            float p = ql.x*kf.x + ql.y*kf.y + ql.z*kf.z + ql.w*kf.w;
            p += __shfl_xor_sync(0xffffffffu, p, 16);
            p += __shfl_xor_sync(0xffffffffu, p, 8);
            p += __shfl_xor_sync(0xffffffffu, p, 4);
            p += __shfl_xor_sync(0xffffffffu, p, 2);
            p += __shfl_xor_sync(0xffffffffu, p, 1);
            if (lane == 0) ssc[t][k] = p;
        }
    }
    __syncthreads();

    const int hcnt = c_hcnt[s];
    for (int hi = 0; hi < hcnt; hi++) {
        const int h = c_hbase[s] + hi;

        for (int i = tid; i < KC * KC; i += 256)
            sks[i >> 5][i & 31] = Sk[(size_t)h * KC * KC + i];
        __syncthreads();

        for (int i = tid; i < 32 * KC; i += 256) {
            const int t = i & 31, j = i >> 5;
            float acc = Sb[h * KC + j];
#pragma unroll
            for (int k = 0; k < KC; k++) acc += ssc[t][k] * sks[j][k];
            shs[t][j] = acc;
        }
        __syncthreads();

        if (tid < 32) {
            float* rowp = shs[tid];
            float m = rowp[0];
#pragma unroll
            for (int j = 1; j < KC; j++) m = fmaxf(m, rowp[j]);
            float sum = 0.0f;
#pragma unroll
            for (int j = 0; j < KC; j++) { float e = expf(rowp[j]-m); rowp[j] = e; sum += e; }
            const float inv = 1.0f / sum;
#pragma unroll
            for (int j = 0; j < KC; j++) rowp[j] *= inv;
        }
        __syncthreads();

        for (int i = tid; i < 63 * DH; i += 256) {
            const int u = i >> 7, col = i & 127;
            const int idx = base + u * dil;
            kv[u][col] = (idx >= 0 && idx < N_)
                ? g_qkv[(size_t)(b * N_ + idx) * QKVW + VOFF + h * DH + col]
                : Vb[h * DH + col];
        }
        __syncthreads();

        const int dq = lane * 4;
#pragma unroll
        for (int tt = 0; tt < 4; tt++) {
            const int t  = wrp + tt * 8;
            const int nt = n0 + t * dil;
            float4 acc = {0.f, 0.f, 0.f, 0.f};
#pragma unroll
            for (int j = 0; j < KC; j++) {
                const float wv = shs[t][j];
                const float4 v = *reinterpret_cast<const float4*>(&kv[t + j][dq]);
                acc.x += wv * v.x; acc.y += wv * v.y;
                acc.z += wv * v.z; acc.w += wv * v.w;
            }
            __nv_bfloat16 h0 = __float2bfloat16(acc.x);
            __nv_bfloat16 h1 = __float2bfloat16(acc.y);
            __nv_bfloat16 h2 = __float2bfloat16(acc.z);
            __nv_bfloat16 h3 = __float2bfloat16(acc.w);
            __nv_bfloat16 l0 = __float2bfloat16(acc.x - __bfloat162float(h0));
            __nv_bfloat16 l1 = __float2bfloat16(acc.y - __bfloat162float(h1));
            __nv_bfloat16 l2 = __float2bfloat16(acc.z - __bfloat162float(h2));
            __nv_bfloat16 l3 = __float2bfloat16(acc.w - __bfloat162float(h3));
            uint2 hv, lv;
            __nv_bfloat162 hp0; hp0.x = h0; hp0.y = h1;
            __nv_bfloat162 hp1; hp1.x = h2; hp1.y = h3;
            __nv_bfloat162 lp0; lp0.x = l0; lp0.y = l1;
            __nv_bfloat162 lp1; lp1.x = l2; lp1.y = l3;
            hv.x = *reinterpret_cast<uint32_t*>(&hp0);
            hv.y = *reinterpret_cast<uint32_t*>(&hp1);
            lv.x = *reinterpret_cast<uint32_t*>(&lp0);
            lv.y = *reinterpret_cast<uint32_t*>(&lp1);
            __nv_bfloat16* orow = gb_at + (size_t)(b * N_ + nt) * KE_C;
            const int col = h * DH + dq;
            *reinterpret_cast<uint2*>(orow + col)          = hv;
            *reinterpret_cast<uint2*>(orow + VW + col)     = hv;
            *reinterpret_cast<uint2*>(orow + 2 * VW + col) = lv;
        }
        __syncthreads();
    }
}

extern "C" void kernel_launch(void* const* d_in, const int* in_sizes, int n_in,
                              void* d_out, int out_size)
{
    const float* query = (const float*)d_in[0];
    const float* key   = (const float*)d_in[1];
    const float* value = (const float*)d_in[2];
    const float* Qk    = (const float*)d_in[3];
    const float* Qb    = (const float*)d_in[4];
    const float* Kk    = (const float*)d_in[5];
    const float* Kb    = (const float*)d_in[6];
    const float* Vk    = (const float*)d_in[7];
    const float* Vb    = (const float*)d_in[8];
    const float* Sk    = (const float*)d_in[9];
    const float* Sb    = (const float*)d_in[10];
    const float* Ck    = (const float*)d_in[11];
    const float* Cb    = (const float*)d_in[12];
    float* out = (float*)d_out;

    __nv_bfloat16 *bw, *bCk;
    cudaGetSymbolAddress((void**)&bw,  gb_w);
    cudaGetSymbolAddress((void**)&bCk, gb_Ck);

    cudaFuncSetAttribute(hmma_qkv_kernel,
        cudaFuncAttributeMaxDynamicSharedMemorySize, SMEM_GEMM);
    cudaFuncSetAttribute(hmma_col_kernel,
        cudaFuncAttributeMaxDynamicSharedMemorySize, SMEM_GEMM);

    const int M = B_ * N_;  // 2048

    {   // activations q/k/v in one launch
        const int pairs = M * DM / 2;
        dim3 grid((pairs + 255) / 256, 3);
        cvt_qkv_kernel<<<grid, 256>>>(query, key, value);
    }
    auto cvt = [](const float* in, __nv_bfloat16* o, int R, int K, int mode) {
        const int pairs = R * K / 2;
        cvt_kernel<<<(pairs + 255) / 256, 256>>>(in, o, pairs, K, mode);
    };
    cvt(Qk, bw,                       SH * DH, DM, 1);
    cvt(Kk, bw + (size_t)KOFF * KE_P, SH * DH, DM, 1);
    cvt(Vk, bw + (size_t)VOFF * KE_P, VW,      DM, 1);
    cvt(Ck, bCk, DM, VW, 1);

    {   // fused Q|K|V projection: grid (24, 16) = 384 CTAs, 2 CTAs/SM
        dim3 grid(QKVW / 128, M / 128);
        hmma_qkv_kernel<<<grid, 128, SMEM_GEMM>>>(Qb, Kb, Vb);
    }
    {   // fused banded attention (writes gb_at bf16x3 directly)
        dim3 grid(32, SH, B_);
        attn_fused_kernel<<<grid, 256>>>(Kb, Vb, Sk, Sb);
    }
    {   // collapse split-K=3: grid (5, 16, 3) = 240 CTAs -> 1 wave @ 2/SM
        dim3 grid(DM / 128, M / 128, ZSPLIT);
        hmma_col_kernel<<<grid, 128, SMEM_GEMM>>>();
    }
    add_bias_kernel<<<(M * DM / 4) / 256, 256>>>(Cb, out);
}

// round 9
// speedup vs baseline: 4.2794x; 1.0606x over previous
#include <cuda_runtime.h>
#include <cuda_bf16.h>
#include <cstdint>

#define B_    2
#define N_    1024
#define DM    640
#define SH    5
#define DH    128
#define NH    14
#define KC    32
#define VW    (NH * DH)       // 1792
#define QKVW  3072
#define KOFF  640
#define VOFF  1280
#define KE_P  (2 * DM)        // 1280  [hi|lo]
#define KE_C  (2 * VW)        // 3584  [hi|lo]
#define ZSPLIT 3

// -------- device scratch --------
__device__ float g_qkv [B_ * N_ * QKVW];
__device__ float g_part[ZSPLIT * B_ * N_ * DM];

__device__ __nv_bfloat16 gb_q [B_ * N_ * KE_P];
__device__ __nv_bfloat16 gb_k [B_ * N_ * KE_P];
__device__ __nv_bfloat16 gb_v [B_ * N_ * KE_P];
__device__ __nv_bfloat16 gb_w [QKVW * KE_P];
__device__ __nv_bfloat16 gb_Ck[DM * KE_C];
__device__ __nv_bfloat16 gb_at[B_ * N_ * KE_C];

__constant__ int c_dil  [SH] = {1, 1, 2, 4, 8};
__constant__ int c_hbase[SH] = {0, 5, 10, 12, 13};
__constant__ int c_hcnt [SH] = {5, 5, 2, 1, 1};

// ============================ helpers ======================================
__device__ __forceinline__ uint32_t smem_u32(const void* p) {
    return (uint32_t)__cvta_generic_to_shared(p);
}
__device__ __forceinline__ void cp_async16(uint32_t saddr, const void* g) {
    asm volatile("cp.async.cg.shared.global [%0], [%1], 16;"
                 :: "r"(saddr), "l"(g) : "memory");
}
#define CP_COMMIT() asm volatile("cp.async.commit_group;" ::: "memory")
#define CP_WAIT1()  asm volatile("cp.async.wait_group 1;"  ::: "memory")

__device__ __forceinline__ void ldmx4(uint32_t* r, uint32_t a) {
    asm volatile("ldmatrix.sync.aligned.m8n8.x4.shared.b16 {%0,%1,%2,%3}, [%4];"
        : "=r"(r[0]), "=r"(r[1]), "=r"(r[2]), "=r"(r[3]) : "r"(a));
}
__device__ __forceinline__ void mma16816(float* d, const uint32_t* a,
                                         const uint32_t b0, const uint32_t b1) {
    asm volatile(
        "mma.sync.aligned.m16n8k16.row.col.f32.bf16.bf16.f32 "
        "{%0,%1,%2,%3}, {%4,%5,%6,%7}, {%8,%9}, {%0,%1,%2,%3};"
        : "+f"(d[0]), "+f"(d[1]), "+f"(d[2]), "+f"(d[3])
        : "r"(a[0]), "r"(a[1]), "r"(a[2]), "r"(a[3]), "r"(b0), "r"(b1));
}

// ---------------------------------------------------------------------------
// HMMA bf16 GEMM over [hi|lo] split operands, 3-phase mainloop:
//   C = sum_c Ahi_c Whi_c^T + Ahi_c Wlo_c^T + Alo_c Whi_c^T
// 128x128 CTA tile, 128 threads (4 warps, 64x64 warp tile), BK=32 orig cols,
// 2-stage cp.async pipeline (4 tiles/stage: Ahi, Alo, Whi, Wlo).
// ---------------------------------------------------------------------------
#define BKT   32
#define LDS_  40                 // 32 + 8 pad (bf16 elems)
#define TSZ   (128 * LDS_ * 2)   // 10240 B per tile
#define STAGE (4 * TSZ)          // 40960 B
#define SMEM_GEMM (2 * STAGE)    // 81920 B -> 2 CTAs/SM

__device__ __forceinline__ void hmma_gemm_body(
    const __nv_bfloat16* __restrict__ A, const __nv_bfloat16* __restrict__ W,
    const float* __restrict__ bias_tile, float* __restrict__ C,
    int nk, int loffA, int loffW, int lda, int ldw, int ldc)
{
    extern __shared__ char smem[];
    const uint32_t smb = smem_u32(smem);

    const int bm = blockIdx.y * 128;
    const int bn = blockIdx.x * 128;
    const int tid = threadIdx.x;                 // 0..127
    const int lane = tid & 31, wid = tid >> 5;   // 4 warps
    const int wm = (wid & 1) * 64;
    const int wn = (wid >> 1) * 64;

    float acc[4][8][4] = {};

    auto issue = [&](int it2) {
        if (it2 < nk) {
            const uint32_t st = smb + (it2 & 1) * STAGE;
            const int cb = it2 * BKT;
#pragma unroll
            for (int i = 0; i < 4; i++) {
                const int idx = tid + i * 128;
                const int row = idx >> 2;
                const int c16 = (idx & 3) * 8;
                const uint32_t so = (uint32_t)(row * LDS_ + c16) * 2;
                const __nv_bfloat16* ar = A + (size_t)(bm + row) * lda + cb + c16;
                const __nv_bfloat16* wr = W + (size_t)(bn + row) * ldw + cb + c16;
                cp_async16(st +           so, ar);
                cp_async16(st + TSZ     + so, ar + loffA);
                cp_async16(st + 2 * TSZ + so, wr);
                cp_async16(st + 3 * TSZ + so, wr + loffW);
            }
        }
        CP_COMMIT();
    };

    issue(0);
    issue(1);

    const int a_row = wm + (lane & 15);
    const int a_kof = (lane >> 4) * 8;
    const int b_row = wn + (lane & 7) + (lane >> 4) * 8;
    const int b_kof = ((lane >> 3) & 1) * 8;

    for (int it = 0; it < nk; ++it) {
        CP_WAIT1();
        __syncthreads();

        const uint32_t st   = smb + (it & 1) * STAGE;
        const uint32_t sAhi = st;
        const uint32_t sAlo = st + TSZ;
        const uint32_t sWhi = st + 2 * TSZ;
        const uint32_t sWlo = st + 3 * TSZ;
#pragma unroll
        for (int ks = 0; ks < 2; ++ks) {
            const int k0 = ks * 16;
            uint32_t ah[4][4], al[4][4], bh[4][4], bl[4][4];
#pragma unroll
            for (int mi = 0; mi < 4; mi++) {
                const uint32_t ro = (uint32_t)((a_row + mi * 16) * LDS_ + k0 + a_kof) * 2;
                ldmx4(ah[mi], sAhi + ro);
                ldmx4(al[mi], sAlo + ro);
            }
#pragma unroll
            for (int g2 = 0; g2 < 4; g2++) {
                const uint32_t ro = (uint32_t)((b_row + g2 * 16) * LDS_ + k0 + b_kof) * 2;
                ldmx4(bh[g2], sWhi + ro);
                ldmx4(bl[g2], sWlo + ro);
            }
            // phase 1: Ahi x Whi
#pragma unroll
            for (int mi = 0; mi < 4; mi++)
#pragma unroll
                for (int ni = 0; ni < 8; ni++)
                    mma16816(acc[mi][ni], ah[mi],
                             bh[ni >> 1][(ni & 1) * 2], bh[ni >> 1][(ni & 1) * 2 + 1]);
            // phase 2: Ahi x Wlo
#pragma unroll
            for (int mi = 0; mi < 4; mi++)
#pragma unroll
                for (int ni = 0; ni < 8; ni++)
                    mma16816(acc[mi][ni], ah[mi],
                             bl[ni >> 1][(ni & 1) * 2], bl[ni >> 1][(ni & 1) * 2 + 1]);
            // phase 3: Alo x Whi
#pragma unroll
            for (int mi = 0; mi < 4; mi++)
#pragma unroll
                for (int ni = 0; ni < 8; ni++)
                    mma16816(acc[mi][ni], al[mi],
                             bh[ni >> 1][(ni & 1) * 2], bh[ni >> 1][(ni & 1) * 2 + 1]);
        }
        __syncthreads();
        issue(it + 2);
    }

    const int g = lane >> 2, t = lane & 3;
#pragma unroll
    for (int mi = 0; mi < 4; mi++) {
        const int row0 = bm + wm + mi * 16 + g;
#pragma unroll
        for (int ni = 0; ni < 8; ni++) {
            const int colL = wn + ni * 8 + t * 2;
            float b0 = 0.f, b1 = 0.f;
            if (bias_tile) { b0 = bias_tile[colL]; b1 = bias_tile[colL + 1]; }
            float2 v0 = {acc[mi][ni][0] + b0, acc[mi][ni][1] + b1};
            float2 v1 = {acc[mi][ni][2] + b0, acc[mi][ni][3] + b1};
            *reinterpret_cast<float2*>(&C[(size_t)row0 * ldc + bn + colL]) = v0;
            *reinterpret_cast<float2*>(&C[(size_t)(row0 + 8) * ldc + bn + colL]) = v1;
        }
    }
}

__global__ __launch_bounds__(128) void hmma_qkv_kernel(
    const float* __restrict__ Qb, const float* __restrict__ Kb,
    const float* __restrict__ Vb)
{
    const int bn = blockIdx.x * 128;
    const __nv_bfloat16* A = (bn < KOFF) ? gb_q : (bn < VOFF) ? gb_k : gb_v;
    const float* bias = (bn < KOFF) ? (Qb + bn)
                      : (bn < VOFF) ? (Kb + bn - KOFF)
                                    : (Vb + bn - VOFF);
    hmma_gemm_body(A, gb_w, bias, g_qkv, DM / BKT, DM, DM, KE_P, KE_P, QKVW);
}

__global__ __launch_bounds__(128) void hmma_col_kernel()
{
    const int z = blockIdx.z;
    const int cstart = (z == 0) ? 0 : (z == 1) ? 19 : 38;   // 56 chunks total
    const int nk     = (z < 2) ? 19 : 18;
    hmma_gemm_body(gb_at + cstart * BKT, gb_Ck + cstart * BKT, nullptr,
                   g_part + (size_t)z * (B_ * N_ * DM),
                   nk, VW, VW, KE_C, KE_C, DM);
}

// ---------------------------------------------------------------------------
// fp32 -> bf16x2 split, row layout [hi(K) | lo(K)], row stride 2K.
// ---------------------------------------------------------------------------
__device__ __forceinline__ void cvt_body(
    const float* __restrict__ inrow, __nv_bfloat16* __restrict__ outrow,
    int k /* pair idx */, int K)
{
    const float2 x = reinterpret_cast<const float2*>(inrow)[k];
    const __nv_bfloat16 h0 = __float2bfloat16(x.x);
    const __nv_bfloat16 h1 = __float2bfloat16(x.y);
    const __nv_bfloat16 l0 = __float2bfloat16(x.x - __bfloat162float(h0));
    const __nv_bfloat16 l1 = __float2bfloat16(x.y - __bfloat162float(h1));
    __nv_bfloat162 hh; hh.x = h0; hh.y = h1;
    __nv_bfloat162 ll; ll.x = l0; ll.y = l1;
    __nv_bfloat162* orow = reinterpret_cast<__nv_bfloat162*>(outrow);
    orow[k] = hh;
    orow[(K >> 1) + k] = ll;
}

__global__ __launch_bounds__(256) void cvt_qkv_kernel(
    const float* __restrict__ q, const float* __restrict__ k,
    const float* __restrict__ v)
{
    const int i = blockIdx.x * 256 + threadIdx.x;
    if (i >= B_ * N_ * DM / 2) return;
    const int which = blockIdx.y;
    const float* in = (which == 0) ? q : (which == 1) ? k : v;
    __nv_bfloat16* out = (which == 0) ? gb_q : (which == 1) ? gb_k : gb_v;
    const int r = i / (DM / 2), kk = i % (DM / 2);
    cvt_body(in + (size_t)r * DM, out + (size_t)r * KE_P, kk, DM);
}

// merged Qk|Kk|Vk weight conversion into gb_w rows [0,640)|[640,1280)|[1280,3072)
__global__ __launch_bounds__(256) void cvt_w_kernel(
    const float* __restrict__ Qk, const float* __restrict__ Kk,
    const float* __restrict__ Vk)
{
    const int i = blockIdx.x * 256 + threadIdx.x;
    if (i >= QKVW * DM / 2) return;
    const int r = i / (DM / 2), kk = i % (DM / 2);
    const float* src = (r < KOFF) ? (Qk + (size_t)r * DM)
                     : (r < VOFF) ? (Kk + (size_t)(r - KOFF) * DM)
                                  : (Vk + (size_t)(r - VOFF) * DM);
    cvt_body(src, gb_w + (size_t)r * KE_P, kk, DM);
}

__global__ __launch_bounds__(256) void cvt_ck_kernel(const float* __restrict__ Ck)
{
    const int i = blockIdx.x * 256 + threadIdx.x;
    if (i >= DM * VW / 2) return;
    const int r = i / (VW / 2), kk = i % (VW / 2);
    cvt_body(Ck + (size_t)r * VW, gb_Ck + (size_t)r * KE_C, kk, VW);
}

__global__ __launch_bounds__(256) void add_bias_kernel(
    const float* __restrict__ Cb, float* __restrict__ out)
{
    const int i = blockIdx.x * 256 + threadIdx.x;
    const float4 p0 = reinterpret_cast<const float4*>(g_part)[i];
    const float4 p1 = reinterpret_cast<const float4*>(g_part + (size_t)B_ * N_ * DM)[i];
    const float4 p2 = reinterpret_cast<const float4*>(g_part + (size_t)2 * B_ * N_ * DM)[i];
    const float4 bb = reinterpret_cast<const float4*>(Cb)[i % (DM / 4)];
    float4 o = {p0.x + p1.x + p2.x + bb.x, p0.y + p1.y + p2.y + bb.y,
                p0.z + p1.z + p2.z + bb.z, p0.w + p1.w + p2.w + bb.w};
    reinterpret_cast<float4*>(out)[i] = o;
}

// ---------------------------------------------------------------------------
// Fused banded attention; epilogue writes bf16x2 [hi|lo] directly to gb_at.
// ---------------------------------------------------------------------------
__global__ __launch_bounds__(256) void attn_fused_kernel(
    const float* __restrict__ Kb, const float* __restrict__ Vb,
    const float* __restrict__ Sk, const float* __restrict__ Sb)
{
    const int z   = blockIdx.x;
    const int s   = blockIdx.y;
    const int b   = blockIdx.z;
    const int tid = threadIdx.x;
    const int lane = tid & 31;
    const int wrp  = tid >> 5;

    const int dil = c_dil[s];
    const int pl  = ((KC - 1) * dil) >> 1;
    const int cpr = 32 / dil;
    const int r0  = z / cpr;
    const int c0  = z % cpr;
    const int n0  = r0 + c0 * 32 * dil;
    const int base = n0 - pl;

    __shared__ float kv [63][DH];
    __shared__ float ssc[32][33];
    __shared__ float sks[32][32];
    __shared__ float shs[32][33];

    for (int i = tid; i < 63 * DH; i += 256) {
        const int u = i >> 7, col = i & 127;
        const int idx = base + u * dil;
        kv[u][col] = (idx >= 0 && idx < N_)
            ? g_qkv[(size_t)(b * N_ + idx) * QKVW + KOFF + s * DH + col]
            : Kb[s * DH + col];
    }
    __syncthreads();

#pragma unroll
    for (int ti = 0; ti < 4; ti++) {
        const int t  = wrp + ti * 8;
        const int nt = n0 + t * dil;
        const float4 ql = *reinterpret_cast<const float4*>(
            g_qkv + (size_t)(b * N_ + nt) * QKVW + s * DH + lane * 4);
#pragma unroll
        for (int k = 0; k < KC; k++) {
            const float4 kf = *reinterpret_cast<const float4*>(&kv[t + k][lane * 4]);
            float p = ql.x*kf.x + ql.y*kf.y + ql.z*kf.z + ql.w*kf.w;
            p += __shfl_xor_sync(0xffffffffu, p, 16);
            p += __shfl_xor_sync(0xffffffffu, p, 8);
            p += __shfl_xor_sync(0xffffffffu, p, 4);
            p += __shfl_xor_sync(0xffffffffu, p, 2);
            p += __shfl_xor_sync(0xffffffffu, p, 1);
            if (lane == 0) ssc[t][k] = p;
        }
    }
    __syncthreads();

    const int hcnt = c_hcnt[s];
    for (int hi = 0; hi < hcnt; hi++) {
        const int h = c_hbase[s] + hi;

        for (int i = tid; i < KC * KC; i += 256)
            sks[i >> 5][i & 31] = Sk[(size_t)h * KC * KC + i];
        __syncthreads();

        for (int i = tid; i < 32 * KC; i += 256) {
            const int t = i & 31, j = i >> 5;
            float acc = Sb[h * KC + j];
#pragma unroll
            for (int k = 0; k < KC; k++) acc += ssc[t][k] * sks[j][k];
            shs[t][j] = acc;
        }
        __syncthreads();

        if (tid < 32) {
            float* rowp = shs[tid];
            float m = rowp[0];
#pragma unroll
            for (int j = 1; j < KC; j++) m = fmaxf(m, rowp[j]);
            float sum = 0.0f;
#pragma unroll
            for (int j = 0; j < KC; j++) { float e = expf(rowp[j]-m); rowp[j] = e; sum += e; }
            const float inv = 1.0f / sum;
#pragma unroll
            for (int j = 0; j < KC; j++) rowp[j] *= inv;
        }
        __syncthreads();

        for (int i = tid; i < 63 * DH; i += 256) {
            const int u = i >> 7, col = i & 127;
            const int idx = base + u * dil;
            kv[u][col] = (idx >= 0 && idx < N_)
                ? g_qkv[(size_t)(b * N_ + idx) * QKVW + VOFF + h * DH + col]
                : Vb[h * DH + col];
        }
        __syncthreads();

        const int dq = lane * 4;
#pragma unroll
        for (int tt = 0; tt < 4; tt++) {
            const int t  = wrp + tt * 8;
            const int nt = n0 + t * dil;
            float4 acc = {0.f, 0.f, 0.f, 0.f};
#pragma unroll
            for (int j = 0; j < KC; j++) {
                const float wv = shs[t][j];
                const float4 v = *reinterpret_cast<const float4*>(&kv[t + j][dq]);
                acc.x += wv * v.x; acc.y += wv * v.y;
                acc.z += wv * v.z; acc.w += wv * v.w;
            }
            __nv_bfloat16 h0 = __float2bfloat16(acc.x);
            __nv_bfloat16 h1 = __float2bfloat16(acc.y);
            __nv_bfloat16 h2 = __float2bfloat16(acc.z);
            __nv_bfloat16 h3 = __float2bfloat16(acc.w);
            __nv_bfloat16 l0 = __float2bfloat16(acc.x - __bfloat162float(h0));
            __nv_bfloat16 l1 = __float2bfloat16(acc.y - __bfloat162float(h1));
            __nv_bfloat16 l2 = __float2bfloat16(acc.z - __bfloat162float(h2));
            __nv_bfloat16 l3 = __float2bfloat16(acc.w - __bfloat162float(h3));
            uint2 hv, lv;
            __nv_bfloat162 hp0; hp0.x = h0; hp0.y = h1;
            __nv_bfloat162 hp1; hp1.x = h2; hp1.y = h3;
            __nv_bfloat162 lp0; lp0.x = l0; lp0.y = l1;
            __nv_bfloat162 lp1; lp1.x = l2; lp1.y = l3;
            hv.x = *reinterpret_cast<uint32_t*>(&hp0);
            hv.y = *reinterpret_cast<uint32_t*>(&hp1);
            lv.x = *reinterpret_cast<uint32_t*>(&lp0);
            lv.y = *reinterpret_cast<uint32_t*>(&lp1);
            __nv_bfloat16* orow = gb_at + (size_t)(b * N_ + nt) * KE_C;
            const int col = h * DH + dq;
            *reinterpret_cast<uint2*>(orow + col)      = hv;
            *reinterpret_cast<uint2*>(orow + VW + col) = lv;
        }
        __syncthreads();
    }
}

extern "C" void kernel_launch(void* const* d_in, const int* in_sizes, int n_in,
                              void* d_out, int out_size)
{
    const float* query = (const float*)d_in[0];
    const float* key   = (const float*)d_in[1];
    const float* value = (const float*)d_in[2];
    const float* Qk    = (const float*)d_in[3];
    const float* Qb    = (const float*)d_in[4];
    const float* Kk    = (const float*)d_in[5];
    const float* Kb    = (const float*)d_in[6];
    const float* Vk    = (const float*)d_in[7];
    const float* Vb    = (const float*)d_in[8];
    const float* Sk    = (const float*)d_in[9];
    const float* Sb    = (const float*)d_in[10];
    const float* Ck    = (const float*)d_in[11];
    const float* Cb    = (const float*)d_in[12];
    float* out = (float*)d_out;

    cudaFuncSetAttribute(hmma_qkv_kernel,
        cudaFuncAttributeMaxDynamicSharedMemorySize, SMEM_GEMM);
    cudaFuncSetAttribute(hmma_col_kernel,
        cudaFuncAttributeMaxDynamicSharedMemorySize, SMEM_GEMM);

    const int M = B_ * N_;  // 2048

    {   // activations q/k/v [hi|lo] in one launch
        const int pairs = M * DM / 2;
        dim3 grid((pairs + 255) / 256, 3);
        cvt_qkv_kernel<<<grid, 256>>>(query, key, value);
    }
    {   // merged Qk|Kk|Vk weight conversion
        const int pairs = QKVW * DM / 2;
        cvt_w_kernel<<<(pairs + 255) / 256, 256>>>(Qk, Kk, Vk);
    }
    {   // Ck conversion
        const int pairs = DM * VW / 2;
        cvt_ck_kernel<<<(pairs + 255) / 256, 256>>>(Ck);
    }
    {   // fused Q|K|V projection: grid (24, 16) = 384 CTAs, 2 CTAs/SM
        dim3 grid(QKVW / 128, M / 128);
        hmma_qkv_kernel<<<grid, 128, SMEM_GEMM>>>(Qb, Kb, Vb);
    }
    {   // fused banded attention (writes gb_at [hi|lo])
        dim3 grid(32, SH, B_);
        attn_fused_kernel<<<grid, 256>>>(Kb, Vb, Sk, Sb);
    }
    {   // collapse split-K=3: grid (5, 16, 3) = 240 CTAs
        dim3 grid(DM / 128, M / 128, ZSPLIT);
        hmma_col_kernel<<<grid, 128, SMEM_GEMM>>>();
    }
    add_bias_kernel<<<(M * DM / 4) / 256, 256>>>(Cb, out);
}

// round 10
// speedup vs baseline: 5.0573x; 1.1818x over previous
#include <cuda_runtime.h>
#include <cuda_fp16.h>
#include <cstdint>

#define B_    2
#define N_    1024
#define DM    640
#define SH    5
#define DH    128
#define NH    14
#define KC    32
#define VW    (NH * DH)       // 1792
#define QKVW  3072
#define KOFF  640
#define VOFF  1280
#define KE_P  (2 * DM)        // 1280  [xh|xl] / [yh|yh]
#define KE_C  (2 * VW)        // 3584
#define ZSPLIT 3

// -------- device scratch --------
__device__ float g_qkv [B_ * N_ * QKVW];
__device__ float g_part[ZSPLIT * B_ * N_ * DM];

__device__ __half gb_q [B_ * N_ * KE_P];
__device__ __half gb_k [B_ * N_ * KE_P];
__device__ __half gb_v [B_ * N_ * KE_P];
__device__ __half gb_w [QKVW * KE_P];
__device__ __half gb_Ck[DM * KE_C];
__device__ __half gb_at[B_ * N_ * KE_C];

__constant__ int c_dil  [SH] = {1, 1, 2, 4, 8};
__constant__ int c_hbase[SH] = {0, 5, 10, 12, 13};
__constant__ int c_hcnt [SH] = {5, 5, 2, 1, 1};

// ============================ helpers ======================================
__device__ __forceinline__ uint32_t smem_u32(const void* p) {
    return (uint32_t)__cvta_generic_to_shared(p);
}
__device__ __forceinline__ void cp_async16(uint32_t saddr, const void* g) {
    asm volatile("cp.async.cg.shared.global [%0], [%1], 16;"
                 :: "r"(saddr), "l"(g) : "memory");
}
#define CP_COMMIT() asm volatile("cp.async.commit_group;" ::: "memory")
#define CP_WAIT1()  asm volatile("cp.async.wait_group 1;"  ::: "memory")

__device__ __forceinline__ void ldmx4(uint32_t* r, uint32_t a) {
    asm volatile("ldmatrix.sync.aligned.m8n8.x4.shared.b16 {%0,%1,%2,%3}, [%4];"
        : "=r"(r[0]), "=r"(r[1]), "=r"(r[2]), "=r"(r[3]) : "r"(a));
}
__device__ __forceinline__ void mma16816(float* d, const uint32_t* a,
                                         const uint32_t b0, const uint32_t b1) {
    asm volatile(
        "mma.sync.aligned.m16n8k16.row.col.f32.f16.f16.f32 "
        "{%0,%1,%2,%3}, {%4,%5,%6,%7}, {%8,%9}, {%0,%1,%2,%3};"
        : "+f"(d[0]), "+f"(d[1]), "+f"(d[2]), "+f"(d[3])
        : "r"(a[0]), "r"(a[1]), "r"(a[2]), "r"(a[3]), "r"(b0), "r"(b1));
}

// ---------------------------------------------------------------------------
// HMMA fp16 GEMM (standard, single phase) over pre-split operands.
// 128x128 CTA tile, 128 threads (4 warps, 64x64 warp tile), BK=64,
// 3-stage cp.async pipeline. 2 CTAs/SM.
// ---------------------------------------------------------------------------
#define BKT   64
#define LDS_  72                 // 64 + 8 pad (fp16 elems)
#define TSZ   (128 * LDS_ * 2)   // 18432 B per tile
#define STAGE (2 * TSZ)          // 36864 B (A + B)
#define SMEM_GEMM (3 * STAGE)    // 110592 B

__device__ __forceinline__ void hmma_gemm_body(
    const __half* __restrict__ A, const __half* __restrict__ W,
    const float* __restrict__ bias_tile, float* __restrict__ C,
    int nk, int lda, int ldw, int ldc)
{
    extern __shared__ char smem[];
    const uint32_t smb = smem_u32(smem);

    const int bm = blockIdx.y * 128;
    const int bn = blockIdx.x * 128;
    const int tid = threadIdx.x;                 // 0..127
    const int lane = tid & 31, wid = tid >> 5;   // 4 warps
    const int wm = (wid & 1) * 64;
    const int wn = (wid >> 1) * 64;

    float acc[4][8][4] = {};

    auto issue = [&](int it2) {
        if (it2 < nk) {
            const uint32_t st = smb + (it2 % 3) * STAGE;
            const int cb = it2 * BKT;
#pragma unroll
            for (int i = 0; i < 8; i++) {
                const int idx = tid + i * 128;
                const int row = idx >> 3;           // 0..127
                const int col = (idx & 7) * 8;      // 0..56
                const uint32_t so = (uint32_t)(row * LDS_ + col) * 2;
                cp_async16(st +       so, A + (size_t)(bm + row) * lda + cb + col);
                cp_async16(st + TSZ + so, W + (size_t)(bn + row) * ldw + cb + col);
            }
        }
        CP_COMMIT();
    };

    issue(0);
    issue(1);

    const int a_row = wm + (lane & 15);
    const int a_kof = (lane >> 4) * 8;
    const int b_row = wn + (lane & 7) + (lane >> 4) * 8;
    const int b_kof = ((lane >> 3) & 1) * 8;

    for (int it = 0; it < nk; ++it) {
        CP_WAIT1();
        __syncthreads();
        issue(it + 2);

        const uint32_t st = smb + (it % 3) * STAGE;
        const uint32_t sA = st;
        const uint32_t sB = st + TSZ;
#pragma unroll
        for (int ks = 0; ks < 4; ++ks) {
            const int k0 = ks * 16;
            uint32_t af[4][4], bf[4][4];
#pragma unroll
            for (int mi = 0; mi < 4; mi++)
                ldmx4(af[mi], sA + (uint32_t)((a_row + mi * 16) * LDS_ + k0 + a_kof) * 2);
#pragma unroll
            for (int g2 = 0; g2 < 4; g2++)
                ldmx4(bf[g2], sB + (uint32_t)((b_row + g2 * 16) * LDS_ + k0 + b_kof) * 2);
#pragma unroll
            for (int mi = 0; mi < 4; mi++)
#pragma unroll
                for (int ni = 0; ni < 8; ni++)
                    mma16816(acc[mi][ni], af[mi],
                             bf[ni >> 1][(ni & 1) * 2], bf[ni >> 1][(ni & 1) * 2 + 1]);
        }
    }

    const int g = lane >> 2, t = lane & 3;
#pragma unroll
    for (int mi = 0; mi < 4; mi++) {
        const int row0 = bm + wm + mi * 16 + g;
#pragma unroll
        for (int ni = 0; ni < 8; ni++) {
            const int colL = wn + ni * 8 + t * 2;
            float b0 = 0.f, b1 = 0.f;
            if (bias_tile) { b0 = bias_tile[colL]; b1 = bias_tile[colL + 1]; }
            float2 v0 = {acc[mi][ni][0] + b0, acc[mi][ni][1] + b1};
            float2 v1 = {acc[mi][ni][2] + b0, acc[mi][ni][3] + b1};
            *reinterpret_cast<float2*>(&C[(size_t)row0 * ldc + bn + colL]) = v0;
            *reinterpret_cast<float2*>(&C[(size_t)(row0 + 8) * ldc + bn + colL]) = v1;
        }
    }
}

__global__ __launch_bounds__(128) void hmma_qkv_kernel(
    const float* __restrict__ Qb, const float* __restrict__ Kb,
    const float* __restrict__ Vb)
{
    const int bn = blockIdx.x * 128;
    const __half* A = (bn < KOFF) ? gb_q : (bn < VOFF) ? gb_k : gb_v;
    const float* bias = (bn < KOFF) ? (Qb + bn)
                      : (bn < VOFF) ? (Kb + bn - KOFF)
                                    : (Vb + bn - VOFF);
    hmma_gemm_body(A, gb_w, bias, g_qkv, KE_P / BKT, KE_P, KE_P, QKVW);
}

__global__ __launch_bounds__(128) void hmma_col_kernel()
{
    const int z = blockIdx.z;                       // 56 chunks: 19/19/18
    const int cstart = (z == 0) ? 0 : (z == 1) ? 19 : 38;
    const int nk     = (z < 2) ? 19 : 18;
    hmma_gemm_body(gb_at + cstart * BKT, gb_Ck + cstart * BKT, nullptr,
                   g_part + (size_t)z * (B_ * N_ * DM),
                   nk, KE_C, KE_C, DM);
}

// ---------------------------------------------------------------------------
// fp32 -> fp16 split conversions, row layout stride 2K.
//   activations: [xh (K) | xl (K)]      weights: [yh (K) | yh (K)]
// ---------------------------------------------------------------------------
__device__ __forceinline__ void cvt_act(
    const float* __restrict__ inrow, __half* __restrict__ outrow, int k, int K)
{
    const float2 x = reinterpret_cast<const float2*>(inrow)[k];
    const __half h0 = __float2half_rn(x.x);
    const __half h1 = __float2half_rn(x.y);
    const __half l0 = __float2half_rn(x.x - __half2float(h0));
    const __half l1 = __float2half_rn(x.y - __half2float(h1));
    __half2 hh; hh.x = h0; hh.y = h1;
    __half2 ll; ll.x = l0; ll.y = l1;
    __half2* orow = reinterpret_cast<__half2*>(outrow);
    orow[k] = hh;
    orow[(K >> 1) + k] = ll;
}
__device__ __forceinline__ void cvt_wt(
    const float* __restrict__ inrow, __half* __restrict__ outrow, int k, int K)
{
    const float2 x = reinterpret_cast<const float2*>(inrow)[k];
    __half2 hh; hh.x = __float2half_rn(x.x); hh.y = __float2half_rn(x.y);
    __half2* orow = reinterpret_cast<__half2*>(outrow);
    orow[k] = hh;
    orow[(K >> 1) + k] = hh;     // duplicate hi
}

__global__ __launch_bounds__(256) void cvt_qkv_kernel(
    const float* __restrict__ q, const float* __restrict__ k,
    const float* __restrict__ v)
{
    const int i = blockIdx.x * 256 + threadIdx.x;
    if (i >= B_ * N_ * DM / 2) return;
    const int which = blockIdx.y;
    const float* in = (which == 0) ? q : (which == 1) ? k : v;
    __half* out = (which == 0) ? gb_q : (which == 1) ? gb_k : gb_v;
    const int r = i / (DM / 2), kk = i % (DM / 2);
    cvt_act(in + (size_t)r * DM, out + (size_t)r * KE_P, kk, DM);
}

__global__ __launch_bounds__(256) void cvt_w_kernel(
    const float* __restrict__ Qk, const float* __restrict__ Kk,
    const float* __restrict__ Vk)
{
    const int i = blockIdx.x * 256 + threadIdx.x;
    if (i >= QKVW * DM / 2) return;
    const int r = i / (DM / 2), kk = i % (DM / 2);
    const float* src = (r < KOFF) ? (Qk + (size_t)r * DM)
                     : (r < VOFF) ? (Kk + (size_t)(r - KOFF) * DM)
                                  : (Vk + (size_t)(r - VOFF) * DM);
    cvt_wt(src, gb_w + (size_t)r * KE_P, kk, DM);
}

__global__ __launch_bounds__(256) void cvt_ck_kernel(const float* __restrict__ Ck)
{
    const int i = blockIdx.x * 256 + threadIdx.x;
    if (i >= DM * VW / 2) return;
    const int r = i / (VW / 2), kk = i % (VW / 2);
    cvt_wt(Ck + (size_t)r * VW, gb_Ck + (size_t)r * KE_C, kk, VW);
}

__global__ __launch_bounds__(256) void add_bias_kernel(
    const float* __restrict__ Cb, float* __restrict__ out)
{
    const int i = blockIdx.x * 256 + threadIdx.x;
    const float4 p0 = reinterpret_cast<const float4*>(g_part)[i];
    const float4 p1 = reinterpret_cast<const float4*>(g_part + (size_t)B_ * N_ * DM)[i];
    const float4 p2 = reinterpret_cast<const float4*>(g_part + (size_t)2 * B_ * N_ * DM)[i];
    const float4 bb = reinterpret_cast<const float4*>(Cb)[i % (DM / 4)];
    float4 o = {p0.x + p1.x + p2.x + bb.x, p0.y + p1.y + p2.y + bb.y,
                p0.z + p1.z + p2.z + bb.z, p0.w + p1.w + p2.w + bb.w};
    reinterpret_cast<float4*>(out)[i] = o;
}

// ---------------------------------------------------------------------------
// Fused banded attention; epilogue writes fp16 [h|l] directly to gb_at.
// ---------------------------------------------------------------------------
__global__ __launch_bounds__(256) void attn_fused_kernel(
    const float* __restrict__ Kb, const float* __restrict__ Vb,
    const float* __restrict__ Sk, const float* __restrict__ Sb)
{
    const int z   = blockIdx.x;
    const int s   = blockIdx.y;
    const int b   = blockIdx.z;
    const int tid = threadIdx.x;
    const int lane = tid & 31;
    const int wrp  = tid >> 5;

    const int dil = c_dil[s];
    const int pl  = ((KC - 1) * dil) >> 1;
    const int cpr = 32 / dil;
    const int r0  = z / cpr;
    const int c0  = z % cpr;
    const int n0  = r0 + c0 * 32 * dil;
    const int base = n0 - pl;

    __shared__ float kv [63][DH];
    __shared__ float ssc[32][33];
    __shared__ float sks[32][32];
    __shared__ float shs[32][33];

    for (int i = tid; i < 63 * DH; i += 256) {
        const int u = i >> 7, col = i & 127;
        const int idx = base + u * dil;
        kv[u][col] = (idx >= 0 && idx < N_)
            ? g_qkv[(size_t)(b * N_ + idx) * QKVW + KOFF + s * DH + col]
            : Kb[s * DH + col];
    }
    __syncthreads();

#pragma unroll
    for (int ti = 0; ti < 4; ti++) {
        const int t  = wrp + ti * 8;
        const int nt = n0 + t * dil;
        const float4 ql = *reinterpret_cast<const float4*>(
            g_qkv + (size_t)(b * N_ + nt) * QKVW + s * DH + lane * 4);
#pragma unroll
        for (int k = 0; k < KC; k++) {
            const float4 kf = *reinterpret_cast<const float4*>(&kv[t + k][lane * 4]);
            float p = ql.x*kf.x + ql.y*kf.y + ql.z*kf.z + ql.w*kf.w;
            p += __shfl_xor_sync(0xffffffffu, p, 16);
            p += __shfl_xor_sync(0xffffffffu, p, 8);
            p += __shfl_xor_sync(0xffffffffu, p, 4);
            p += __shfl_xor_sync(0xffffffffu, p, 2);
            p += __shfl_xor_sync(0xffffffffu, p, 1);
            if (lane == 0) ssc[t][k] = p;
        }
    }
    __syncthreads();

    const int hcnt = c_hcnt[s];
    for (int hi = 0; hi < hcnt; hi++) {
        const int h = c_hbase[s] + hi;

        for (int i = tid; i < KC * KC; i += 256)
            sks[i >> 5][i & 31] = Sk[(size_t)h * KC * KC + i];
        __syncthreads();

        for (int i = tid; i < 32 * KC; i += 256) {
            const int t = i & 31, j = i >> 5;
            float acc = Sb[h * KC + j];
#pragma unroll
            for (int k = 0; k < KC; k++) acc += ssc[t][k] * sks[j][k];
            shs[t][j] = acc;
        }
        __syncthreads();

        if (tid < 32) {
            float* rowp = shs[tid];
            float m = rowp[0];
#pragma unroll
            for (int j = 1; j < KC; j++) m = fmaxf(m, rowp[j]);
            float sum = 0.0f;
#pragma unroll
            for (int j = 0; j < KC; j++) { float e = expf(rowp[j]-m); rowp[j] = e; sum += e; }
            const float inv = 1.0f / sum;
#pragma unroll
            for (int j = 0; j < KC; j++) rowp[j] *= inv;
        }
        __syncthreads();

        for (int i = tid; i < 63 * DH; i += 256) {
            const int u = i >> 7, col = i & 127;
            const int idx = base + u * dil;
            kv[u][col] = (idx >= 0 && idx < N_)
                ? g_qkv[(size_t)(b * N_ + idx) * QKVW + VOFF + h * DH + col]
                : Vb[h * DH + col];
        }
        __syncthreads();

        const int dq = lane * 4;
#pragma unroll
        for (int tt = 0; tt < 4; tt++) {
            const int t  = wrp + tt * 8;
            const int nt = n0 + t * dil;
            float4 acc = {0.f, 0.f, 0.f, 0.f};
#pragma unroll
            for (int j = 0; j < KC; j++) {
                const float wv = shs[t][j];
                const float4 v = *reinterpret_cast<const float4*>(&kv[t + j][dq]);
                acc.x += wv * v.x; acc.y += wv * v.y;
                acc.z += wv * v.z; acc.w += wv * v.w;
            }
            const __half h0 = __float2half_rn(acc.x);
            const __half h1 = __float2half_rn(acc.y);
            const __half h2 = __float2half_rn(acc.z);
            const __half h3 = __float2half_rn(acc.w);
            const __half l0 = __float2half_rn(acc.x - __half2float(h0));
            const __half l1 = __float2half_rn(acc.y - __half2float(h1));
            const __half l2 = __float2half_rn(acc.z - __half2float(h2));
            const __half l3 = __float2half_rn(acc.w - __half2float(h3));
            __half2 hp0; hp0.x = h0; hp0.y = h1;
            __half2 hp1; hp1.x = h2; hp1.y = h3;
            __half2 lp0; lp0.x = l0; lp0.y = l1;
            __half2 lp1; lp1.x = l2; lp1.y = l3;
            uint2 hv, lv;
            hv.x = *reinterpret_cast<uint32_t*>(&hp0);
            hv.y = *reinterpret_cast<uint32_t*>(&hp1);
            lv.x = *reinterpret_cast<uint32_t*>(&lp0);
            lv.y = *reinterpret_cast<uint32_t*>(&lp1);
            __half* orow = gb_at + (size_t)(b * N_ + nt) * KE_C;
            const int col = h * DH + dq;
            *reinterpret_cast<uint2*>(orow + col)      = hv;
            *reinterpret_cast<uint2*>(orow + VW + col) = lv;
        }
        __syncthreads();
    }
}

extern "C" void kernel_launch(void* const* d_in, const int* in_sizes, int n_in,
                              void* d_out, int out_size)
{
    const float* query = (const float*)d_in[0];
    const float* key   = (const float*)d_in[1];
    const float* value = (const float*)d_in[2];
    const float* Qk    = (const float*)d_in[3];
    const float* Qb    = (const float*)d_in[4];
    const float* Kk    = (const float*)d_in[5];
    const float* Kb    = (const float*)d_in[6];
    const float* Vk    = (const float*)d_in[7];
    const float* Vb    = (const float*)d_in[8];
    const float* Sk    = (const float*)d_in[9];
    const float* Sb    = (const float*)d_in[10];
    const float* Ck    = (const float*)d_in[11];
    const float* Cb    = (const float*)d_in[12];
    float* out = (float*)d_out;

    cudaFuncSetAttribute(hmma_qkv_kernel,
        cudaFuncAttributeMaxDynamicSharedMemorySize, SMEM_GEMM);
    cudaFuncSetAttribute(hmma_col_kernel,
        cudaFuncAttributeMaxDynamicSharedMemorySize, SMEM_GEMM);

    const int M = B_ * N_;  // 2048

    {   // activations q/k/v [xh|xl] in one launch
        const int pairs = M * DM / 2;
        dim3 grid((pairs + 255) / 256, 3);
        cvt_qkv_kernel<<<grid, 256>>>(query, key, value);
    }
    {   // merged Qk|Kk|Vk weight conversion [yh|yh]
        const int pairs = QKVW * DM / 2;
        cvt_w_kernel<<<(pairs + 255) / 256, 256>>>(Qk, Kk, Vk);
    }
    {   // Ck conversion [yh|yh]
        const int pairs = DM * VW / 2;
        cvt_ck_kernel<<<(pairs + 255) / 256, 256>>>(Ck);
    }
    {   // fused Q|K|V projection: grid (24, 16) = 384 CTAs, 2 CTAs/SM
        dim3 grid(QKVW / 128, M / 128);
        hmma_qkv_kernel<<<grid, 128, SMEM_GEMM>>>(Qb, Kb, Vb);
    }
    {   // fused banded attention (writes gb_at [h|l])
        dim3 grid(32, SH, B_);
        attn_fused_kernel<<<grid, 256>>>(Kb, Vb, Sk, Sb);
    }
    {   // collapse split-K=3: grid (5, 16, 3) = 240 CTAs
        dim3 grid(DM / 128, M / 128, ZSPLIT);
        hmma_col_kernel<<<grid, 128, SMEM_GEMM>>>();
    }
    add_bias_kernel<<<(M * DM / 4) / 256, 256>>>(Cb, out);
}

// round 11
// speedup vs baseline: 5.5145x; 1.0904x over previous
#include <cuda_runtime.h>
#include <cuda_fp16.h>
#include <cstdint>

#define B_    2
#define N_    1024
#define DM    640
#define SH    5
#define DH    128
#define NH    14
#define KC    32
#define VW    (NH * DH)       // 1792
#define QKVW  3072
#define KOFF  640
#define VOFF  1280
#define KE_P  (2 * DM)        // 1280  [xh|xl] / [yh|yh]
#define KE_C  (2 * VW)        // 3584
#define ZSPLIT 4

// -------- device scratch --------
__device__ float g_qkv [B_ * N_ * QKVW];
__device__ float g_part[ZSPLIT * B_ * N_ * DM];

__device__ __half gb_q [B_ * N_ * KE_P];
__device__ __half gb_k [B_ * N_ * KE_P];
__device__ __half gb_v [B_ * N_ * KE_P];
__device__ __half gb_w [QKVW * KE_P];
__device__ __half gb_Ck[DM * KE_C];
__device__ __half gb_at[B_ * N_ * KE_C];

__constant__ int c_dil  [SH] = {1, 1, 2, 4, 8};
__constant__ int c_hbase[SH] = {0, 5, 10, 12, 13};
__constant__ int c_hcnt [SH] = {5, 5, 2, 1, 1};

// ============================ helpers ======================================
__device__ __forceinline__ uint32_t smem_u32(const void* p) {
    return (uint32_t)__cvta_generic_to_shared(p);
}
__device__ __forceinline__ void cp_async16(uint32_t saddr, const void* g) {
    asm volatile("cp.async.cg.shared.global [%0], [%1], 16;"
                 :: "r"(saddr), "l"(g) : "memory");
}
#define CP_COMMIT() asm volatile("cp.async.commit_group;" ::: "memory")
#define CP_WAIT1()  asm volatile("cp.async.wait_group 1;"  ::: "memory")

__device__ __forceinline__ void ldmx4(uint32_t* r, uint32_t a) {
    asm volatile("ldmatrix.sync.aligned.m8n8.x4.shared.b16 {%0,%1,%2,%3}, [%4];"
        : "=r"(r[0]), "=r"(r[1]), "=r"(r[2]), "=r"(r[3]) : "r"(a));
}
__device__ __forceinline__ void mma16816(float* d, const uint32_t* a,
                                         const uint32_t b0, const uint32_t b1) {
    asm volatile(
        "mma.sync.aligned.m16n8k16.row.col.f32.f16.f16.f32 "
        "{%0,%1,%2,%3}, {%4,%5,%6,%7}, {%8,%9}, {%0,%1,%2,%3};"
        : "+f"(d[0]), "+f"(d[1]), "+f"(d[2]), "+f"(d[3])
        : "r"(a[0]), "r"(a[1]), "r"(a[2]), "r"(a[3]), "r"(b0), "r"(b1));
}

// ---------------------------------------------------------------------------
// HMMA fp16 GEMM over pre-split operands.
// 128x128 CTA tile, 128 threads (4 warps, 64x64 warp tile), BK=32,
// 3-stage cp.async pipeline. 61.4 KB smem -> 3 CTAs/SM (12 warps/SM).
// ---------------------------------------------------------------------------
#define BKT   32
#define LDS_  40                 // 32 + 8 pad (fp16 elems)
#define TSZ   (128 * LDS_ * 2)   // 10240 B per tile
#define STAGE (2 * TSZ)          // 20480 B (A + B)
#define SMEM_GEMM (3 * STAGE)    // 61440 B

__device__ __forceinline__ void hmma_gemm_body(
    const __half* __restrict__ A, const __half* __restrict__ W,
    const float* __restrict__ bias_tile, float* __restrict__ C,
    int nk, int lda, int ldw, int ldc)
{
    extern __shared__ char smem[];
    const uint32_t smb = smem_u32(smem);

    const int bm = blockIdx.y * 128;
    const int bn = blockIdx.x * 128;
    const int tid = threadIdx.x;                 // 0..127
    const int lane = tid & 31, wid = tid >> 5;   // 4 warps
    const int wm = (wid & 1) * 64;
    const int wn = (wid >> 1) * 64;

    float acc[4][8][4] = {};

    auto issue = [&](int it2) {
        if (it2 < nk) {
            const uint32_t st = smb + (it2 % 3) * STAGE;
            const int cb = it2 * BKT;
#pragma unroll
            for (int i = 0; i < 4; i++) {
                const int idx = tid + i * 128;
                const int row = idx >> 2;           // 0..127
                const int col = (idx & 3) * 8;      // 0,8,16,24
                const uint32_t so = (uint32_t)(row * LDS_ + col) * 2;
                cp_async16(st +       so, A + (size_t)(bm + row) * lda + cb + col);
                cp_async16(st + TSZ + so, W + (size_t)(bn + row) * ldw + cb + col);
            }
        }
        CP_COMMIT();
    };

    issue(0);
    issue(1);

    const int a_row = wm + (lane & 15);
    const int a_kof = (lane >> 4) * 8;
    const int b_row = wn + (lane & 7) + (lane >> 4) * 8;
    const int b_kof = ((lane >> 3) & 1) * 8;

    for (int it = 0; it < nk; ++it) {
        CP_WAIT1();
        __syncthreads();
        issue(it + 2);

        const uint32_t st = smb + (it % 3) * STAGE;
        const uint32_t sA = st;
        const uint32_t sB = st + TSZ;
#pragma unroll
        for (int ks = 0; ks < 2; ++ks) {
            const int k0 = ks * 16;
            uint32_t af[4][4], bf[4][4];
#pragma unroll
            for (int mi = 0; mi < 4; mi++)
                ldmx4(af[mi], sA + (uint32_t)((a_row + mi * 16) * LDS_ + k0 + a_kof) * 2);
#pragma unroll
            for (int g2 = 0; g2 < 4; g2++)
                ldmx4(bf[g2], sB + (uint32_t)((b_row + g2 * 16) * LDS_ + k0 + b_kof) * 2);
#pragma unroll
            for (int mi = 0; mi < 4; mi++)
#pragma unroll
                for (int ni = 0; ni < 8; ni++)
                    mma16816(acc[mi][ni], af[mi],
                             bf[ni >> 1][(ni & 1) * 2], bf[ni >> 1][(ni & 1) * 2 + 1]);
        }
    }

    const int g = lane >> 2, t = lane & 3;
#pragma unroll
    for (int mi = 0; mi < 4; mi++) {
        const int row0 = bm + wm + mi * 16 + g;
#pragma unroll
        for (int ni = 0; ni < 8; ni++) {
            const int colL = wn + ni * 8 + t * 2;
            float b0 = 0.f, b1 = 0.f;
            if (bias_tile) { b0 = bias_tile[colL]; b1 = bias_tile[colL + 1]; }
            float2 v0 = {acc[mi][ni][0] + b0, acc[mi][ni][1] + b1};
            float2 v1 = {acc[mi][ni][2] + b0, acc[mi][ni][3] + b1};
            *reinterpret_cast<float2*>(&C[(size_t)row0 * ldc + bn + colL]) = v0;
            *reinterpret_cast<float2*>(&C[(size_t)(row0 + 8) * ldc + bn + colL]) = v1;
        }
    }
}

__global__ __launch_bounds__(128, 3) void hmma_qkv_kernel(
    const float* __restrict__ Qb, const float* __restrict__ Kb,
    const float* __restrict__ Vb)
{
    const int bn = blockIdx.x * 128;
    const __half* A = (bn < KOFF) ? gb_q : (bn < VOFF) ? gb_k : gb_v;
    const float* bias = (bn < KOFF) ? (Qb + bn)
                      : (bn < VOFF) ? (Kb + bn - KOFF)
                                    : (Vb + bn - VOFF);
    hmma_gemm_body(A, gb_w, bias, g_qkv, KE_P / BKT, KE_P, KE_P, QKVW);
}

__global__ __launch_bounds__(128, 3) void hmma_col_kernel()
{
    const int z = blockIdx.z;            // 56 chunks of 32: 14 per z
    const int cstart = z * 14;
    hmma_gemm_body(gb_at + cstart * BKT, gb_Ck + cstart * BKT, nullptr,
                   g_part + (size_t)z * (B_ * N_ * DM),
                   14, KE_C, KE_C, DM);
}

// ---------------------------------------------------------------------------
// fp32 -> fp16 split conversions, row layout stride 2K.
//   activations: [xh (K) | xl (K)]      weights: [yh (K) | yh (K)]
// ---------------------------------------------------------------------------
__device__ __forceinline__ void cvt_act(
    const float* __restrict__ inrow, __half* __restrict__ outrow, int k, int K)
{
    const float2 x = reinterpret_cast<const float2*>(inrow)[k];
    const __half h0 = __float2half_rn(x.x);
    const __half h1 = __float2half_rn(x.y);
    const __half l0 = __float2half_rn(x.x - __half2float(h0));
    const __half l1 = __float2half_rn(x.y - __half2float(h1));
    __half2 hh; hh.x = h0; hh.y = h1;
    __half2 ll; ll.x = l0; ll.y = l1;
    __half2* orow = reinterpret_cast<__half2*>(outrow);
    orow[k] = hh;
    orow[(K >> 1) + k] = ll;
}
__device__ __forceinline__ void cvt_wt(
    const float* __restrict__ inrow, __half* __restrict__ outrow, int k, int K)
{
    const float2 x = reinterpret_cast<const float2*>(inrow)[k];
    __half2 hh; hh.x = __float2half_rn(x.x); hh.y = __float2half_rn(x.y);
    __half2* orow = reinterpret_cast<__half2*>(outrow);
    orow[k] = hh;
    orow[(K >> 1) + k] = hh;     // duplicate hi
}

__global__ __launch_bounds__(256) void cvt_qkv_kernel(
    const float* __restrict__ q, const float* __restrict__ k,
    const float* __restrict__ v)
{
    const int i = blockIdx.x * 256 + threadIdx.x;
    if (i >= B_ * N_ * DM / 2) return;
    const int which = blockIdx.y;
    const float* in = (which == 0) ? q : (which == 1) ? k : v;
    __half* out = (which == 0) ? gb_q : (which == 1) ? gb_k : gb_v;
    const int r = i / (DM / 2), kk = i % (DM / 2);
    cvt_act(in + (size_t)r * DM, out + (size_t)r * KE_P, kk, DM);
}

__global__ __launch_bounds__(256) void cvt_w_kernel(
    const float* __restrict__ Qk, const float* __restrict__ Kk,
    const float* __restrict__ Vk)
{
    const int i = blockIdx.x * 256 + threadIdx.x;
    if (i >= QKVW * DM / 2) return;
    const int r = i / (DM / 2), kk = i % (DM / 2);
    const float* src = (r < KOFF) ? (Qk + (size_t)r * DM)
                     : (r < VOFF) ? (Kk + (size_t)(r - KOFF) * DM)
                                  : (Vk + (size_t)(r - VOFF) * DM);
    cvt_wt(src, gb_w + (size_t)r * KE_P, kk, DM);
}

__global__ __launch_bounds__(256) void cvt_ck_kernel(const float* __restrict__ Ck)
{
    const int i = blockIdx.x * 256 + threadIdx.x;
    if (i >= DM * VW / 2) return;
    const int r = i / (VW / 2), kk = i % (VW / 2);
    cvt_wt(Ck + (size_t)r * VW, gb_Ck + (size_t)r * KE_C, kk, VW);
}

__global__ __launch_bounds__(256) void add_bias_kernel(
    const float* __restrict__ Cb, float* __restrict__ out)
{
    const int i = blockIdx.x * 256 + threadIdx.x;
    const float4 p0 = reinterpret_cast<const float4*>(g_part)[i];
    const float4 p1 = reinterpret_cast<const float4*>(g_part + (size_t)B_ * N_ * DM)[i];
    const float4 p2 = reinterpret_cast<const float4*>(g_part + (size_t)2 * B_ * N_ * DM)[i];
    const float4 p3 = reinterpret_cast<const float4*>(g_part + (size_t)3 * B_ * N_ * DM)[i];
    const float4 bb = reinterpret_cast<const float4*>(Cb)[i % (DM / 4)];
    float4 o = {p0.x + p1.x + p2.x + p3.x + bb.x,
                p0.y + p1.y + p2.y + p3.y + bb.y,
                p0.z + p1.z + p2.z + p3.z + bb.z,
                p0.w + p1.w + p2.w + p3.w + bb.w};
    reinterpret_cast<float4*>(out)[i] = o;
}

// ---------------------------------------------------------------------------
// Fused banded attention; epilogue writes fp16 [h|l] directly to gb_at.
// ---------------------------------------------------------------------------
__global__ __launch_bounds__(256) void attn_fused_kernel(
    const float* __restrict__ Kb, const float* __restrict__ Vb,
    const float* __restrict__ Sk, const float* __restrict__ Sb)
{
    const int z   = blockIdx.x;
    const int s   = blockIdx.y;
    const int b   = blockIdx.z;
    const int tid = threadIdx.x;
    const int lane = tid & 31;
    const int wrp  = tid >> 5;

    const int dil = c_dil[s];
    const int pl  = ((KC - 1) * dil) >> 1;
    const int cpr = 32 / dil;
    const int r0  = z / cpr;
    const int c0  = z % cpr;
    const int n0  = r0 + c0 * 32 * dil;
    const int base = n0 - pl;

    __shared__ float kv [63][DH];
    __shared__ float ssc[32][33];
    __shared__ float sks[32][32];
    __shared__ float shs[32][33];

    for (int i = tid; i < 63 * DH; i += 256) {
        const int u = i >> 7, col = i & 127;
        const int idx = base + u * dil;
        kv[u][col] = (idx >= 0 && idx < N_)
            ? g_qkv[(size_t)(b * N_ + idx) * QKVW + KOFF + s * DH + col]
            : Kb[s * DH + col];
    }
    __syncthreads();

#pragma unroll
    for (int ti = 0; ti < 4; ti++) {
        const int t  = wrp + ti * 8;
        const int nt = n0 + t * dil;
        const float4 ql = *reinterpret_cast<const float4*>(
            g_qkv + (size_t)(b * N_ + nt) * QKVW + s * DH + lane * 4);
#pragma unroll
        for (int k = 0; k < KC; k++) {
            const float4 kf = *reinterpret_cast<const float4*>(&kv[t + k][lane * 4]);
            float p = ql.x*kf.x + ql.y*kf.y + ql.z*kf.z + ql.w*kf.w;
            p += __shfl_xor_sync(0xffffffffu, p, 16);
            p += __shfl_xor_sync(0xffffffffu, p, 8);
            p += __shfl_xor_sync(0xffffffffu, p, 4);
            p += __shfl_xor_sync(0xffffffffu, p, 2);
            p += __shfl_xor_sync(0xffffffffu, p, 1);
            if (lane == 0) ssc[t][k] = p;
        }
    }
    __syncthreads();

    const int hcnt = c_hcnt[s];
    for (int hi = 0; hi < hcnt; hi++) {
        const int h = c_hbase[s] + hi;

        for (int i = tid; i < KC * KC; i += 256)
            sks[i >> 5][i & 31] = Sk[(size_t)h * KC * KC + i];
        __syncthreads();

        for (int i = tid; i < 32 * KC; i += 256) {
            const int t = i & 31, j = i >> 5;
            float acc = Sb[h * KC + j];
#pragma unroll
            for (int k = 0; k < KC; k++) acc += ssc[t][k] * sks[j][k];
            shs[t][j] = acc;
        }
        __syncthreads();

        if (tid < 32) {
            float* rowp = shs[tid];
            float m = rowp[0];
#pragma unroll
            for (int j = 1; j < KC; j++) m = fmaxf(m, rowp[j]);
            float sum = 0.0f;
#pragma unroll
            for (int j = 0; j < KC; j++) { float e = expf(rowp[j]-m); rowp[j] = e; sum += e; }
            const float inv = 1.0f / sum;
#pragma unroll
            for (int j = 0; j < KC; j++) rowp[j] *= inv;
        }
        __syncthreads();

        for (int i = tid; i < 63 * DH; i += 256) {
            const int u = i >> 7, col = i & 127;
            const int idx = base + u * dil;
            kv[u][col] = (idx >= 0 && idx < N_)
                ? g_qkv[(size_t)(b * N_ + idx) * QKVW + VOFF + h * DH + col]
                : Vb[h * DH + col];
        }
        __syncthreads();

        const int dq = lane * 4;
#pragma unroll
        for (int tt = 0; tt < 4; tt++) {
            const int t  = wrp + tt * 8;
            const int nt = n0 + t * dil;
            float4 acc = {0.f, 0.f, 0.f, 0.f};
#pragma unroll
            for (int j = 0; j < KC; j++) {
                const float wv = shs[t][j];
                const float4 v = *reinterpret_cast<const float4*>(&kv[t + j][dq]);
                acc.x += wv * v.x; acc.y += wv * v.y;
                acc.z += wv * v.z; acc.w += wv * v.w;
            }
            const __half h0 = __float2half_rn(acc.x);
            const __half h1 = __float2half_rn(acc.y);
            const __half h2 = __float2half_rn(acc.z);
            const __half h3 = __float2half_rn(acc.w);
            const __half l0 = __float2half_rn(acc.x - __half2float(h0));
            const __half l1 = __float2half_rn(acc.y - __half2float(h1));
            const __half l2 = __float2half_rn(acc.z - __half2float(h2));
            const __half l3 = __float2half_rn(acc.w - __half2float(h3));
            __half2 hp0; hp0.x = h0; hp0.y = h1;
            __half2 hp1; hp1.x = h2; hp1.y = h3;
            __half2 lp0; lp0.x = l0; lp0.y = l1;
            __half2 lp1; lp1.x = l2; lp1.y = l3;
            uint2 hv, lv;
            hv.x = *reinterpret_cast<uint32_t*>(&hp0);
            hv.y = *reinterpret_cast<uint32_t*>(&hp1);
            lv.x = *reinterpret_cast<uint32_t*>(&lp0);
            lv.y = *reinterpret_cast<uint32_t*>(&lp1);
            __half* orow = gb_at + (size_t)(b * N_ + nt) * KE_C;
            const int col = h * DH + dq;
            *reinterpret_cast<uint2*>(orow + col)      = hv;
            *reinterpret_cast<uint2*>(orow + VW + col) = lv;
        }
        __syncthreads();
    }
}

extern "C" void kernel_launch(void* const* d_in, const int* in_sizes, int n_in,
                              void* d_out, int out_size)
{
    const float* query = (const float*)d_in[0];
    const float* key   = (const float*)d_in[1];
    const float* value = (const float*)d_in[2];
    const float* Qk    = (const float*)d_in[3];
    const float* Qb    = (const float*)d_in[4];
    const float* Kk    = (const float*)d_in[5];
    const float* Kb    = (const float*)d_in[6];
    const float* Vk    = (const float*)d_in[7];
    const float* Vb    = (const float*)d_in[8];
    const float* Sk    = (const float*)d_in[9];
    const float* Sb    = (const float*)d_in[10];
    const float* Ck    = (const float*)d_in[11];
    const float* Cb    = (const float*)d_in[12];
    float* out = (float*)d_out;

    cudaFuncSetAttribute(hmma_qkv_kernel,
        cudaFuncAttributeMaxDynamicSharedMemorySize, SMEM_GEMM);
    cudaFuncSetAttribute(hmma_col_kernel,
        cudaFuncAttributeMaxDynamicSharedMemorySize, SMEM_GEMM);

    const int M = B_ * N_;  // 2048

    {   // activations q/k/v [xh|xl] in one launch
        const int pairs = M * DM / 2;
        dim3 grid((pairs + 255) / 256, 3);
        cvt_qkv_kernel<<<grid, 256>>>(query, key, value);
    }
    {   // merged Qk|Kk|Vk weight conversion [yh|yh]
        const int pairs = QKVW * DM / 2;
        cvt_w_kernel<<<(pairs + 255) / 256, 256>>>(Qk, Kk, Vk);
    }
    {   // Ck conversion [yh|yh]
        const int pairs = DM * VW / 2;
        cvt_ck_kernel<<<(pairs + 255) / 256, 256>>>(Ck);
    }
    {   // fused Q|K|V projection: grid (24, 16) = 384 CTAs, 3 CTAs/SM
        dim3 grid(QKVW / 128, M / 128);
        hmma_qkv_kernel<<<grid, 128, SMEM_GEMM>>>(Qb, Kb, Vb);
    }
    {   // fused banded attention (writes gb_at [h|l])
        dim3 grid(32, SH, B_);
        attn_fused_kernel<<<grid, 256>>>(Kb, Vb, Sk, Sb);
    }
    {   // collapse split-K=4: grid (5, 16, 4) = 320 CTAs
        dim3 grid(DM / 128, M / 128, ZSPLIT);
        hmma_col_kernel<<<grid, 128, SMEM_GEMM>>>();
    }
    add_bias_kernel<<<(M * DM / 4) / 256, 256>>>(Cb, out);
}